// round 13
// baseline (speedup 1.0000x reference)
#include <cuda_runtime.h>
#include <cuda_fp16.h>

#define Bk 64
#define Pk 12
#define Qk 12
#define Nk 1024
#define Dk 64

typedef unsigned int uint32;

__device__ __forceinline__ uint32 packh2(float a, float b) {
    __half2 h = __floats2half2_rn(a, b);
    return *(uint32*)&h;
}
__device__ __forceinline__ void mma_f16(float* d, uint4 a, uint32 b0, uint32 b1) {
    asm("mma.sync.aligned.m16n8k16.row.col.f32.f16.f16.f32 "
        "{%0,%1,%2,%3},{%4,%5,%6,%7},{%8,%9},{%0,%1,%2,%3};"
        : "+f"(d[0]), "+f"(d[1]), "+f"(d[2]), "+f"(d[3])
        : "r"(a.x), "r"(a.y), "r"(a.z), "r"(a.w), "r"(b0), "r"(b1));
}
__device__ __forceinline__ float tanh_a(float z) {
    float y;
    asm("tanh.approx.f32 %0, %1;" : "=f"(y) : "f"(z));
    return y;
}
__device__ __forceinline__ float sigm_a(float z) {
    return fmaf(0.5f, tanh_a(0.5f * z), 0.5f);
}
__device__ __forceinline__ float tanh_fast(float z) {
    z = fminf(fmaxf(z, -15.f), 15.f);
    float e = __expf(-2.f * z);
    return __fdividef(1.f - e, 1.f + e);
}

// ---------------- scratch ----------------
__device__ float g_se[Nk * Dk];
__device__ float g_te[Bk * Pk * Dk];
__device__ float g_s2[Bk * Nk * Dk];
__device__ uint32 g_XeH[(size_t)Bk * Pk * 16 * 2048];
__device__ uint32 g_gWh[2][8192];
__device__ uint32 g_cWh[2][4096];
__device__ float g_alpha[65 * 64];
__device__ float g_beta[65 * 64];
__device__ float g_ts[64];

// ---------------- weight folding + fp16 frag packing ----------------
__global__ void k_prep(const float* __restrict__ Wg1, const float* __restrict__ Wc1,
                       const float* __restrict__ Wg2, const float* __restrict__ Wc2) {
    int tid = blockIdx.x * blockDim.x + threadIdx.x;
    int stride = gridDim.x * blockDim.x;
    for (int i = tid; i < 16384; i += stride) {
        int v = i & 3, lane = (i >> 2) & 31, ktp = (i >> 7) & 1;
        int n8 = (i >> 8) & 15, pt = (i >> 12) & 1, l = (i >> 13) & 1;
        int kt = 2 * ktp + (v >> 1), reg = v & 1;
        int g = lane >> 2, tig = lane & 3;
        int k0 = kt * 16 + 2 * tig + 8 * reg;
        int n = n8 * 8 + g;
        const float* W = l ? Wg2 : Wg1;
        int r0 = pt * 64;
        float f0 = W[(r0 + k0) * 128 + n] + W[(r0 + 128 + k0) * 128 + n];
        float f1 = W[(r0 + k0 + 1) * 128 + n] + W[(r0 + 129 + k0) * 128 + n];
        g_gWh[l][((pt * 16 + n8) * 2 + ktp) * 128 + lane * 4 + v] = packh2(f0, f1);
    }
    for (int i = tid; i < 8192; i += stride) {
        int v = i & 3, lane = (i >> 2) & 31, ktp = (i >> 7) & 1;
        int n8 = (i >> 8) & 7, pt = (i >> 11) & 1, l = (i >> 12) & 1;
        int kt = 2 * ktp + (v >> 1), reg = v & 1;
        int g = lane >> 2, tig = lane & 3;
        int k0 = kt * 16 + 2 * tig + 8 * reg;
        int n = n8 * 8 + g;
        const float* W = l ? Wc2 : Wc1;
        int r0 = pt * 64;
        float f0 = W[(r0 + k0) * 64 + n] + W[(r0 + 128 + k0) * 64 + n];
        float f1 = W[(r0 + k0 + 1) * 64 + n] + W[(r0 + 129 + k0) * 64 + n];
        g_cWh[l][((pt * 8 + n8) * 2 + ktp) * 128 + lane * 4 + v] = packh2(f0, f1);
    }
}

// ---------------- fc_in piecewise-linear precompute ----------------
__global__ void k_prep_seg(const float* __restrict__ W1, const float* __restrict__ b1,
                           const float* __restrict__ W2, const float* __restrict__ b2) {
    __shared__ float w1s[64], b1s[64], tsr[64];
    __shared__ int rnk[64];
    int tid = threadIdx.x;
    if (tid < 64) { w1s[tid] = W1[tid]; b1s[tid] = b1[tid]; }
    __syncthreads();
    if (tid < 64) {
        float w = w1s[tid];
        tsr[tid] = (w != 0.f) ? (-b1s[tid] / w) : __int_as_float(0x7f800000);
    }
    __syncthreads();
    if (tid < 64) {
        float t = tsr[tid];
        int r = 0;
        for (int d = 0; d < 64; d++) {
            float td = tsr[d];
            r += (td < t) || (td == t && d < tid);
        }
        rnk[tid] = r;
        g_ts[r] = t;
    }
    __syncthreads();
    for (int idx = tid; idx < 65 * 64; idx += blockDim.x) {
        int s = idx >> 6, c = idx & 63;
        float a = 0.f, bt = 0.f;
        for (int d = 0; d < 64; d++) {
            float w = w1s[d];
            bool act = (w > 0.f) ? (rnk[d] < s)
                     : ((w < 0.f) ? (rnk[d] >= s) : (b1s[d] > 0.f));
            if (act) {
                float w2 = W2[d * 64 + c];
                a = fmaf(w, w2, a);
                bt = fmaf(b1s[d], w2, bt);
            }
        }
        g_alpha[idx] = a;
        g_beta[idx] = bt + b2[c];
    }
}

// ---------------- spatial embedding ----------------
__global__ void k_se(const float* __restrict__ SE, const float* __restrict__ W1,
                     const float* __restrict__ b1, const float* __restrict__ W2,
                     const float* __restrict__ b2) {
    __shared__ float xs[64], hs[64];
    int n = blockIdx.x, d = threadIdx.x;
    xs[d] = SE[n * 64 + d];
    __syncthreads();
    float a = b1[d];
#pragma unroll 8
    for (int k = 0; k < 64; k++) a = fmaf(xs[k], W1[k * 64 + d], a);
    hs[d] = fmaxf(a, 0.f);
    __syncthreads();
    float o = b2[d];
#pragma unroll 8
    for (int k = 0; k < 64; k++) o = fmaf(hs[k], W2[k * 64 + d], o);
    g_se[n * 64 + d] = o;
}

// ---------------- temporal embedding ----------------
__global__ void k_te(const int* __restrict__ TE, const float* __restrict__ W1,
                     const float* __restrict__ b1, const float* __restrict__ W2,
                     const float* __restrict__ b2) {
    __shared__ float hs[64];
    int row = blockIdx.x;
    int b = row / Pk, p = row - b * Pk;
    int d = threadIdx.x;
    int base = (b * (Pk + Qk) + p) * 2;
    int t0 = TE[base], t1 = TE[base + 1];
    float a = W1[t0 * 64 + d] + W1[(7 + t1) * 64 + d] + b1[d];
    hs[d] = fmaxf(a, 0.f);
    __syncthreads();
    float o = b2[d];
#pragma unroll 8
    for (int k = 0; k < 64; k++) o = fmaf(hs[k], W2[k * 64 + d], o);
    g_te[row * 64 + d] = o;
}

// ---------------- FC_in: closed-form affine -> fp16 frag output ----------------
__global__ __launch_bounds__(256) void k_fc_in_h(const float* __restrict__ X) {
    __shared__ float sA[65 * 64], sB[65 * 64], sTs[64], sTe[64];
    __shared__ float sXs[1024];
    __shared__ int sSeg[1024];
    int tid = threadIdx.x;
    int bp = blockIdx.x;
    {
        const float4* a = (const float4*)g_alpha;
        const float4* b = (const float4*)g_beta;
        float4* da = (float4*)sA;
        float4* db = (float4*)sB;
        for (int i = tid; i < 1040; i += 256) { da[i] = a[i]; db[i] = b[i]; }
    }
    if (tid < 64) { sTs[tid] = g_ts[tid]; sTe[tid] = g_te[bp * 64 + tid]; }
    __syncthreads();
    for (int i = tid; i < 1024; i += 256) {
        float x = X[(size_t)bp * 1024 + i];
        sXs[i] = x;
        int sg = 0;
#pragma unroll 16
        for (int k = 0; k < 64; k++) sg += (sTs[k] < x);
        sSeg[i] = sg;
    }
    __syncthreads();
#pragma unroll 4
    for (int it = 0; it < 32; it++) {
        int sl = it * 256 + tid;
        int nt = sl >> 9, r9 = sl & 511;
        int mt = r9 >> 7, kt = (r9 >> 5) & 3, s = r9 & 31;
        int g = s >> 2, tig = s & 3;
        int n0 = nt * 64 + 16 * mt + g, n1 = n0 + 8;
        int c0 = 16 * kt + 2 * tig, c1 = c0 + 8;
        float x0 = sXs[n0], x1 = sXs[n1];
        int s0 = sSeg[n0] * 64, s1 = sSeg[n1] * 64;
        float2 a00 = *(const float2*)&sA[s0 + c0], b00 = *(const float2*)&sB[s0 + c0];
        float2 a01 = *(const float2*)&sA[s0 + c1], b01 = *(const float2*)&sB[s0 + c1];
        float2 a10 = *(const float2*)&sA[s1 + c0], b10 = *(const float2*)&sB[s1 + c0];
        float2 a11 = *(const float2*)&sA[s1 + c1], b11 = *(const float2*)&sB[s1 + c1];
        float2 se00 = *(const float2*)&g_se[n0 * 64 + c0];
        float2 se01 = *(const float2*)&g_se[n0 * 64 + c1];
        float2 se10 = *(const float2*)&g_se[n1 * 64 + c0];
        float2 se11 = *(const float2*)&g_se[n1 * 64 + c1];
        float2 te0 = *(const float2*)&sTe[c0];
        float2 te1 = *(const float2*)&sTe[c1];
        uint32 u0 = packh2(fmaf(x0, a00.x, b00.x) + se00.x + te0.x,
                           fmaf(x0, a00.y, b00.y) + se00.y + te0.y);
        uint32 u1 = packh2(fmaf(x1, a10.x, b10.x) + se10.x + te0.x,
                           fmaf(x1, a10.y, b10.y) + se10.y + te0.y);
        uint32 u2 = packh2(fmaf(x0, a01.x, b01.x) + se01.x + te1.x,
                           fmaf(x0, a01.y, b01.y) + se01.y + te1.y);
        uint32 u3 = packh2(fmaf(x1, a11.x, b11.x) + se11.x + te1.x,
                           fmaf(x1, a11.y, b11.y) + se11.y + te1.y);
        *(uint4*)&g_XeH[(size_t)(bp * 16 + nt) * 2048 + (mt * 4 + kt) * 128 + s * 4] =
            make_uint4(u0, u1, u2, u3);
    }
}

// ---------------- GRU phase helpers (fine-N tiling: 16 warps, nq in 0..7) ----------------
__device__ __forceinline__ void phaseA(
        const uint32* __restrict__ Xc, const uint32* __restrict__ Sf,
        const uint32* __restrict__ gWl,
        float (&aR)[2][4], float (&aU)[2][4], int lane, int mp, int nq) {
#pragma unroll
    for (int mt = 0; mt < 2; mt++)
#pragma unroll
        for (int v = 0; v < 4; v++) { aR[mt][v] = 0.f; aU[mt][v] = 0.f; }
#pragma unroll
    for (int ktp = 0; ktp < 2; ktp++) {
        uint4 bRx = *(const uint4*)&gWl[(nq * 2 + ktp) * 128 + lane * 4];
        uint4 bUx = *(const uint4*)&gWl[((8 + nq) * 2 + ktp) * 128 + lane * 4];
        uint4 bRs = *(const uint4*)&gWl[((16 + nq) * 2 + ktp) * 128 + lane * 4];
        uint4 bUs = *(const uint4*)&gWl[((24 + nq) * 2 + ktp) * 128 + lane * 4];
#pragma unroll
        for (int k2 = 0; k2 < 2; k2++) {
            int kt = 2 * ktp + k2;
            uint4 ax[2], as2[2];
#pragma unroll
            for (int mt = 0; mt < 2; mt++) {
                int toff = ((2 * mp + mt) * 4 + kt) * 128 + lane * 4;
                ax[mt] = *(const uint4*)&Xc[toff];
                as2[mt] = *(const uint4*)&Sf[toff];
            }
            uint32 rx0 = k2 ? bRx.z : bRx.x, rx1 = k2 ? bRx.w : bRx.y;
            uint32 rs0 = k2 ? bRs.z : bRs.x, rs1 = k2 ? bRs.w : bRs.y;
            uint32 ux0 = k2 ? bUx.z : bUx.x, ux1 = k2 ? bUx.w : bUx.y;
            uint32 us0 = k2 ? bUs.z : bUs.x, us1 = k2 ? bUs.w : bUs.y;
#pragma unroll
            for (int mt = 0; mt < 2; mt++) {
                mma_f16(aR[mt], ax[mt], rx0, rx1);
                mma_f16(aR[mt], as2[mt], rs0, rs1);
                mma_f16(aU[mt], ax[mt], ux0, ux1);
                mma_f16(aU[mt], as2[mt], us0, us1);
            }
        }
    }
}

__device__ __forceinline__ void epiA(
        const float (&aR)[2][4], const float (&aU)[2][4],
        const float (&bgr)[2], const float (&bgu)[2],
        const float (&sr)[2][4], float (&uv)[2][4],
        uint32* __restrict__ Rf, int mp, int nq, int g, int tig) {
#pragma unroll
    for (int mt = 0; mt < 2; mt++) {
        float r0 = sigm_a(aR[mt][0] + bgr[0]);
        float r1 = sigm_a(aR[mt][1] + bgr[1]);
        float r2 = sigm_a(aR[mt][2] + bgr[0]);
        float r3 = sigm_a(aR[mt][3] + bgr[1]);
        uv[mt][0] = sigm_a(aU[mt][0] + bgu[0]);
        uv[mt][1] = sigm_a(aU[mt][1] + bgu[1]);
        uv[mt][2] = sigm_a(aU[mt][2] + bgu[0]);
        uv[mt][3] = sigm_a(aU[mt][3] + bgu[1]);
        uint32 o0 = packh2(r0 * sr[mt][0], r1 * sr[mt][1]);
        uint32 o1 = packh2(r2 * sr[mt][2], r3 * sr[mt][3]);
        *(uint2*)&Rf[((2 * mp + mt) * 4 + (nq >> 1)) * 128 + (4 * g + tig) * 4 + 2 * (nq & 1)] =
            make_uint2(o0, o1);
    }
}

__device__ __forceinline__ void phaseB(
        const uint32* __restrict__ Xc, const uint32* __restrict__ Rf,
        const uint32* __restrict__ cWl, float (&aC)[2][4], int lane, int mp, int nq) {
#pragma unroll
    for (int mt = 0; mt < 2; mt++)
#pragma unroll
        for (int v = 0; v < 4; v++) aC[mt][v] = 0.f;
#pragma unroll
    for (int ktp = 0; ktp < 2; ktp++) {
        uint4 bCx = *(const uint4*)&cWl[(nq * 2 + ktp) * 128 + lane * 4];
        uint4 bCs = *(const uint4*)&cWl[((8 + nq) * 2 + ktp) * 128 + lane * 4];
#pragma unroll
        for (int k2 = 0; k2 < 2; k2++) {
            int kt = 2 * ktp + k2;
            uint4 ax[2], ar[2];
#pragma unroll
            for (int mt = 0; mt < 2; mt++) {
                int toff = ((2 * mp + mt) * 4 + kt) * 128 + lane * 4;
                ax[mt] = *(const uint4*)&Xc[toff];
                ar[mt] = *(const uint4*)&Rf[toff];
            }
            uint32 x0 = k2 ? bCx.z : bCx.x, x1 = k2 ? bCx.w : bCx.y;
            uint32 s0 = k2 ? bCs.z : bCs.x, s1 = k2 ? bCs.w : bCs.y;
#pragma unroll
            for (int mt = 0; mt < 2; mt++) {
                mma_f16(aC[mt], ax[mt], x0, x1);
                mma_f16(aC[mt], ar[mt], s0, s1);
            }
        }
    }
}

__device__ __forceinline__ void epiB(
        const float (&aC)[2][4], const float (&bcc)[2],
        const float (&uv)[2][4], float (&sr)[2][4],
        uint32* __restrict__ Sf, int mp, int nq, int g, int tig) {
#pragma unroll
    for (int mt = 0; mt < 2; mt++) {
        float c0 = tanh_fast(aC[mt][0] + bcc[0]);
        float c1 = tanh_fast(aC[mt][1] + bcc[1]);
        float c2 = tanh_fast(aC[mt][2] + bcc[0]);
        float c3 = tanh_fast(aC[mt][3] + bcc[1]);
        float n0 = fmaf(uv[mt][0], sr[mt][0] - c0, c0);
        float n1 = fmaf(uv[mt][1], sr[mt][1] - c1, c1);
        float n2 = fmaf(uv[mt][2], sr[mt][2] - c2, c2);
        float n3 = fmaf(uv[mt][3], sr[mt][3] - c3, c3);
        sr[mt][0] = n0; sr[mt][1] = n1; sr[mt][2] = n2; sr[mt][3] = n3;
        uint32 o0 = packh2(n0, n1);
        uint32 o1 = packh2(n2, n3);
        *(uint2*)&Sf[((2 * mp + mt) * 4 + (nq >> 1)) * 128 + (4 * g + tig) * 4 + 2 * (nq & 1)] =
            make_uint2(o0, o1);
    }
}

// ---------------- fused 2-layer DCGRU scan: 512 threads, fine-N tiling ----------------
// smem (uint32): gW0 8192 | gW1 8192 | cW0 4096 | cW1 4096 | Xf 2x2048 | S1f 2x2048 |
//                S2f 2048 | Rf1 2048 | Rf2 2048 | biases 384 floats -> 39296 u32
__global__ __launch_bounds__(512, 1) void k_scan(
        const float* __restrict__ bg1_, const float* __restrict__ bc1_,
        const float* __restrict__ bg2_, const float* __restrict__ bc2_) {
    extern __shared__ uint32 smu[];
    uint32* gW0 = smu;
    uint32* gW1 = smu + 8192;
    uint32* cW0 = smu + 16384;
    uint32* cW1 = smu + 20480;
    uint32* Xf  = smu + 24576;
    uint32* S1f = smu + 28672;
    uint32* S2f = smu + 32768;
    uint32* Rf1 = smu + 34816;
    uint32* Rf2 = smu + 36864;
    float*  sb  = (float*)(smu + 38912);

    int tid = threadIdx.x;
    {
        const uint4* s0 = (const uint4*)g_gWh[0];
        const uint4* s1 = (const uint4*)g_gWh[1];
        uint4* d0 = (uint4*)gW0; uint4* d1 = (uint4*)gW1;
        for (int i = tid; i < 2048; i += 512) { d0[i] = s0[i]; d1[i] = s1[i]; }
        const uint4* c0 = (const uint4*)g_cWh[0];
        const uint4* c1 = (const uint4*)g_cWh[1];
        uint4* e0 = (uint4*)cW0; uint4* e1 = (uint4*)cW1;
        for (int i = tid; i < 1024; i += 512) { e0[i] = c0[i]; e1[i] = c1[i]; }
    }
    if (tid < 128) { sb[tid] = bg1_[tid]; sb[128 + tid] = bg2_[tid]; }
    else if (tid >= 256 && tid < 320) sb[tid] = bc1_[tid - 256];
    else if (tid >= 320 && tid < 384) sb[tid] = bc2_[tid - 320];
    {
        uint4 z = make_uint4(0, 0, 0, 0);
        uint4* z1 = (uint4*)S1f; uint4* z2 = (uint4*)S2f;
        for (int i = tid; i < 1024; i += 512) z1[i] = z;
        for (int i = tid; i < 512; i += 512) z2[i] = z;
    }
    int row0 = blockIdx.x * 64;
    int b = row0 >> 10, ntb = (row0 >> 6) & 15;
    {   // x(0) -> Xf[0], x(1) -> Xf[1]
        const uint4* s0 = (const uint4*)&g_XeH[(size_t)(b * Pk * 16 + ntb) * 2048];
        const uint4* s1 = (const uint4*)&g_XeH[(size_t)((b * Pk + 1) * 16 + ntb) * 2048];
        ((uint4*)Xf)[tid] = s0[tid];
        ((uint4*)(Xf + 2048))[tid] = s1[tid];
    }
    __syncthreads();

    int lane = tid & 31, w = tid >> 5;
    int mp = w & 1, nq = w >> 1, g = lane >> 2, tig = lane & 3;

    float bgr1[2], bgu1[2], bcc1[2];
    float bgr2[2], bgu2[2], bcc2[2];
    {
        int j = 8 * nq + 2 * tig;
        bgr1[0] = sb[j];        bgr1[1] = sb[j + 1];
        bgu1[0] = sb[64 + j];   bgu1[1] = sb[64 + j + 1];
        bgr2[0] = sb[128 + j];  bgr2[1] = sb[128 + j + 1];
        bgu2[0] = sb[192 + j];  bgu2[1] = sb[192 + j + 1];
        bcc1[0] = sb[256 + j];  bcc1[1] = sb[256 + j + 1];
        bcc2[0] = sb[320 + j];  bcc2[1] = sb[320 + j + 1];
    }
    float s1r[2][4], s2r[2][4];
#pragma unroll
    for (int mt = 0; mt < 2; mt++)
#pragma unroll
        for (int v = 0; v < 4; v++) { s1r[mt][v] = 0.f; s2r[mt][v] = 0.f; }

    float uv1[2][4], uv2[2][4];

    // ---- standalone L1 at t=0: x in Xf[0], zero state in S1f[1], writes S1f[0] ----
    {
        float aR[2][4], aU[2][4], aC[2][4];
        phaseA(Xf, S1f + 2048, gW0, aR, aU, lane, mp, nq);
        epiA(aR, aU, bgr1, bgu1, s1r, uv1, Rf1, mp, nq, g, tig);
        __syncthreads();
        phaseB(Xf, Rf1, cW0, aC, lane, mp, nq);
        epiB(aC, bcc1, uv1, s1r, S1f, mp, nq, g, tig);
        __syncthreads();
    }

    // ---- fused supersteps: L1 at t=k+1 with L2 at t=k ----
    for (int k = 0; k <= 10; k++) {
        int p = k & 1;
        uint32* Xc  = Xf + ((k + 1) & 1) * 2048;
        uint32* S1c = S1f + p * 2048;
        uint32* S1n = S1f + (p ^ 1) * 2048;
        uint4 pf = make_uint4(0, 0, 0, 0);
        bool inst = (k + 2 < Pk);
        if (inst) {
            const uint4* s = (const uint4*)&g_XeH[(size_t)((b * Pk + k + 2) * 16 + ntb) * 2048];
            pf = s[tid];
        }
        {
            float aR[2][4], aU[2][4];
            phaseA(Xc, S1c, gW0, aR, aU, lane, mp, nq);
            epiA(aR, aU, bgr1, bgu1, s1r, uv1, Rf1, mp, nq, g, tig);
        }
        {
            float aR[2][4], aU[2][4];
            phaseA(S1c, S2f, gW1, aR, aU, lane, mp, nq);
            epiA(aR, aU, bgr2, bgu2, s2r, uv2, Rf2, mp, nq, g, tig);
        }
        if (inst) ((uint4*)(Xf + (k & 1) * 2048))[tid] = pf;
        __syncthreads();
        {
            float aC[2][4];
            phaseB(Xc, Rf1, cW0, aC, lane, mp, nq);
            epiB(aC, bcc1, uv1, s1r, S1n, mp, nq, g, tig);
        }
        {
            float aC[2][4];
            phaseB(S1c, Rf2, cW1, aC, lane, mp, nq);
            epiB(aC, bcc2, uv2, s2r, S2f, mp, nq, g, tig);
        }
        __syncthreads();
    }

    // ---- standalone L2 at t=11: input S1(11) in S1f[1] ----
    {
        float aR[2][4], aU[2][4], aC[2][4];
        phaseA(S1f + 2048, S2f, gW1, aR, aU, lane, mp, nq);
        epiA(aR, aU, bgr2, bgu2, s2r, uv2, Rf2, mp, nq, g, tig);
        __syncthreads();
        phaseB(S1f + 2048, Rf2, cW1, aC, lane, mp, nq);
        epiB(aC, bcc2, uv2, s2r, S2f, mp, nq, g, tig);
    }

    // write final layer-2 state (warp owns cols 8nq+2tig..+1)
#pragma unroll
    for (int mt = 0; mt < 2; mt++) {
        int j = 8 * nq + 2 * tig;
        int r0g = row0 + (2 * mp + mt) * 16 + g;
        *(float2*)&g_s2[(size_t)r0g * 64 + j]       = make_float2(s2r[mt][0], s2r[mt][1]);
        *(float2*)&g_s2[(size_t)(r0g + 8) * 64 + j] = make_float2(s2r[mt][2], s2r[mt][3]);
    }
}

// ---------------- FC_out ----------------
__global__ __launch_bounds__(256) void k_fc_out(
        const float* __restrict__ W1, const float* __restrict__ b1,
        const float* __restrict__ W2, const float* __restrict__ b2,
        float* __restrict__ out) {
    __shared__ float sW1[64 * 64];
    __shared__ float sHin[64 * 64];
    __shared__ float sH[64 * 65];
    __shared__ float sW2[64 * 12];
    __shared__ float sb1v[64], sb2v[12];
    int tid = threadIdx.x;
    for (int i = tid; i < 4096; i += 256) sW1[i] = W1[i];
    for (int i = tid; i < 768; i += 256) sW2[i] = W2[i];
    if (tid < 64) sb1v[tid] = b1[tid];
    if (tid < 12) sb2v[tid] = b2[tid];
    int row0 = blockIdx.x * 64;
    for (int i4 = tid; i4 < 1024; i4 += 256) {
        int i = i4 >> 4, c = (i4 & 15) << 2;
        *(float4*)&sHin[i * 64 + c] = *(const float4*)&g_s2[(size_t)(row0 + i) * 64 + c];
    }
    __syncthreads();
    int lane = tid & 31, w = tid >> 5, c0 = lane * 2;
    float acc[8][2];
#pragma unroll
    for (int ri = 0; ri < 8; ri++) { acc[ri][0] = 0.f; acc[ri][1] = 0.f; }
#pragma unroll 8
    for (int k = 0; k < 64; k++) {
        float2 wv = *(const float2*)&sW1[k * 64 + c0];
#pragma unroll
        for (int ri = 0; ri < 8; ri++) {
            float h = sHin[(w + ri * 8) * 64 + k];
            acc[ri][0] = fmaf(h, wv.x, acc[ri][0]);
            acc[ri][1] = fmaf(h, wv.y, acc[ri][1]);
        }
    }
#pragma unroll
    for (int ri = 0; ri < 8; ri++) {
        int i = w + ri * 8;
        sH[i * 65 + c0]     = fmaxf(acc[ri][0] + sb1v[c0], 0.f);
        sH[i * 65 + c0 + 1] = fmaxf(acc[ri][1] + sb1v[c0 + 1], 0.f);
    }
    __syncthreads();
    int i = tid >> 2;
    int q0 = (tid & 3) * 3;
    float a0 = sb2v[q0], a1 = sb2v[q0 + 1], a2 = sb2v[q0 + 2];
#pragma unroll 8
    for (int k = 0; k < 64; k++) {
        float h = sH[i * 65 + k];
        a0 = fmaf(h, sW2[k * 12 + q0],     a0);
        a1 = fmaf(h, sW2[k * 12 + q0 + 1], a1);
        a2 = fmaf(h, sW2[k * 12 + q0 + 2], a2);
    }
    int r = row0 + i, b = r >> 10, n = r & 1023;
    out[(((size_t)b * Qk + q0)     << 10) + n] = a0;
    out[(((size_t)b * Qk + q0 + 1) << 10) + n] = a1;
    out[(((size_t)b * Qk + q0 + 2) << 10) + n] = a2;
}

// ---------------- launch ----------------
extern "C" void kernel_launch(void* const* d_in, const int* in_sizes, int n_in,
                              void* d_out, int out_size) {
    const float* X     = (const float*)d_in[0];
    const float* SE    = (const float*)d_in[3];
    const float* W_se1 = (const float*)d_in[4];  const float* b_se1 = (const float*)d_in[5];
    const float* W_se2 = (const float*)d_in[6];  const float* b_se2 = (const float*)d_in[7];
    const float* W_te1 = (const float*)d_in[8];  const float* b_te1 = (const float*)d_in[9];
    const float* W_te2 = (const float*)d_in[10]; const float* b_te2 = (const float*)d_in[11];
    const float* W_in1 = (const float*)d_in[12]; const float* b_in1 = (const float*)d_in[13];
    const float* W_in2 = (const float*)d_in[14]; const float* b_in2 = (const float*)d_in[15];
    const float* Wg1   = (const float*)d_in[16]; const float* bg1   = (const float*)d_in[17];
    const float* Wc1   = (const float*)d_in[18]; const float* bc1   = (const float*)d_in[19];
    const float* Wg2   = (const float*)d_in[20]; const float* bg2   = (const float*)d_in[21];
    const float* Wc2   = (const float*)d_in[22]; const float* bc2   = (const float*)d_in[23];
    const float* W_o1  = (const float*)d_in[24]; const float* b_o1  = (const float*)d_in[25];
    const float* W_o2  = (const float*)d_in[26]; const float* b_o2  = (const float*)d_in[27];
    const int*   TE    = (const int*)d_in[28];
    float* out = (float*)d_out;

    const size_t scan_smem = (size_t)39296 * 4;   // 157,184 B
    cudaFuncSetAttribute(k_scan, cudaFuncAttributeMaxDynamicSharedMemorySize,
                         (int)scan_smem);

    k_prep<<<64, 256>>>(Wg1, Wc1, Wg2, Wc2);
    k_prep_seg<<<1, 256>>>(W_in1, b_in1, W_in2, b_in2);
    k_se<<<Nk, 64>>>(SE, W_se1, b_se1, W_se2, b_se2);
    k_te<<<Bk * Pk, 64>>>(TE, W_te1, b_te1, W_te2, b_te2);
    k_fc_in_h<<<Bk * Pk, 256>>>(X);

    k_scan<<<Bk * Nk / 64, 512, scan_smem>>>(bg1, bc1, bg2, bc2);

    k_fc_out<<<Bk * Nk / 64, 256>>>(W_o1, b_o1, W_o2, b_o2, out);
}

// round 14
// speedup vs baseline: 1.1024x; 1.1024x over previous
#include <cuda_runtime.h>
#include <cuda_fp16.h>

#define Bk 64
#define Pk 12
#define Qk 12
#define Nk 1024
#define Dk 64

typedef unsigned int uint32;

__device__ __forceinline__ uint32 packh2(float a, float b) {
    __half2 h = __floats2half2_rn(a, b);
    return *(uint32*)&h;
}
__device__ __forceinline__ void mma_f16(float* d, uint4 a, uint32 b0, uint32 b1) {
    asm("mma.sync.aligned.m16n8k16.row.col.f32.f16.f16.f32 "
        "{%0,%1,%2,%3},{%4,%5,%6,%7},{%8,%9},{%0,%1,%2,%3};"
        : "+f"(d[0]), "+f"(d[1]), "+f"(d[2]), "+f"(d[3])
        : "r"(a.x), "r"(a.y), "r"(a.z), "r"(a.w), "r"(b0), "r"(b1));
}
__device__ __forceinline__ float tanh_a(float z) {
    float y;
    asm("tanh.approx.f32 %0, %1;" : "=f"(y) : "f"(z));
    return y;
}
__device__ __forceinline__ float sigm_a(float z) {
    return fmaf(0.5f, tanh_a(0.5f * z), 0.5f);
}
__device__ __forceinline__ float tanh_fast(float z) {
    z = fminf(fmaxf(z, -15.f), 15.f);
    float e = __expf(-2.f * z);
    return __fdividef(1.f - e, 1.f + e);
}

// ---------------- scratch ----------------
__device__ float g_se[Nk * Dk];
__device__ float g_te[Bk * Pk * Dk];
__device__ uint32 g_XeH[(size_t)Bk * Pk * 16 * 2048];
__device__ uint32 g_gWh[2][8192];
__device__ uint32 g_cWh[2][4096];
__device__ float g_alpha[65 * 64];
__device__ float g_beta[65 * 64];
__device__ float g_ts[64];

// ---------------- fused setup: weight packing + fc_in closed form + se + te ----------------
__global__ __launch_bounds__(256) void k_setup(
        const float* __restrict__ Wg1, const float* __restrict__ Wc1,
        const float* __restrict__ Wg2, const float* __restrict__ Wc2,
        const float* __restrict__ Wi1, const float* __restrict__ bi1,
        const float* __restrict__ Wi2, const float* __restrict__ bi2,
        const float* __restrict__ SE,
        const float* __restrict__ Wse1, const float* __restrict__ bse1,
        const float* __restrict__ Wse2, const float* __restrict__ bse2,
        const int* __restrict__ TE,
        const float* __restrict__ Wte1, const float* __restrict__ bte1,
        const float* __restrict__ Wte2, const float* __restrict__ bte2) {
    __shared__ float sh[512];
    __shared__ int shi[64];
    int bid = blockIdx.x;
    int t = threadIdx.x;
    if (bid < 48) {
        // ---- weight folding + fp16 frag packing ----
        int tid = bid * 256 + t;
        int stride = 48 * 256;
        for (int i = tid; i < 16384; i += stride) {
            int v = i & 3, lane = (i >> 2) & 31, ktp = (i >> 7) & 1;
            int n8 = (i >> 8) & 15, pt = (i >> 12) & 1, l = (i >> 13) & 1;
            int kt = 2 * ktp + (v >> 1), reg = v & 1;
            int g = lane >> 2, tig = lane & 3;
            int k0 = kt * 16 + 2 * tig + 8 * reg;
            int n = n8 * 8 + g;
            const float* W = l ? Wg2 : Wg1;
            int r0 = pt * 64;
            float f0 = W[(r0 + k0) * 128 + n] + W[(r0 + 128 + k0) * 128 + n];
            float f1 = W[(r0 + k0 + 1) * 128 + n] + W[(r0 + 129 + k0) * 128 + n];
            g_gWh[l][((pt * 16 + n8) * 2 + ktp) * 128 + lane * 4 + v] = packh2(f0, f1);
        }
        for (int i = tid; i < 8192; i += stride) {
            int v = i & 3, lane = (i >> 2) & 31, ktp = (i >> 7) & 1;
            int n8 = (i >> 8) & 7, pt = (i >> 11) & 1, l = (i >> 12) & 1;
            int kt = 2 * ktp + (v >> 1), reg = v & 1;
            int g = lane >> 2, tig = lane & 3;
            int k0 = kt * 16 + 2 * tig + 8 * reg;
            int n = n8 * 8 + g;
            const float* W = l ? Wc2 : Wc1;
            int r0 = pt * 64;
            float f0 = W[(r0 + k0) * 64 + n] + W[(r0 + 128 + k0) * 64 + n];
            float f1 = W[(r0 + k0 + 1) * 64 + n] + W[(r0 + 129 + k0) * 64 + n];
            g_cWh[l][((pt * 8 + n8) * 2 + ktp) * 128 + lane * 4 + v] = packh2(f0, f1);
        }
    } else if (bid == 48) {
        // ---- fc_in piecewise-linear precompute ----
        float* w1s = sh;
        float* b1s = sh + 64;
        float* tsr = sh + 128;
        if (t < 64) { w1s[t] = Wi1[t]; b1s[t] = bi1[t]; }
        __syncthreads();
        if (t < 64) {
            float w = w1s[t];
            tsr[t] = (w != 0.f) ? (-b1s[t] / w) : __int_as_float(0x7f800000);
        }
        __syncthreads();
        if (t < 64) {
            float tv = tsr[t];
            int r = 0;
            for (int d = 0; d < 64; d++) {
                float td = tsr[d];
                r += (td < tv) || (td == tv && d < t);
            }
            shi[t] = r;
            g_ts[r] = tv;
        }
        __syncthreads();
        for (int idx = t; idx < 65 * 64; idx += 256) {
            int s = idx >> 6, c = idx & 63;
            float a = 0.f, bt = 0.f;
            for (int d = 0; d < 64; d++) {
                float w = w1s[d];
                bool act = (w > 0.f) ? (shi[d] < s)
                         : ((w < 0.f) ? (shi[d] >= s) : (b1s[d] > 0.f));
                if (act) {
                    float w2 = Wi2[d * 64 + c];
                    a = fmaf(w, w2, a);
                    bt = fmaf(b1s[d], w2, bt);
                }
            }
            g_alpha[idx] = a;
            g_beta[idx] = bt + bi2[c];
        }
    } else if (bid < 305) {
        // ---- spatial embedding: 4 n-rows per block ----
        float* xs = sh;
        float* hs = sh + 256;
        int nl = t >> 6, d = t & 63;
        int n = (bid - 49) * 4 + nl;
        xs[nl * 64 + d] = SE[n * 64 + d];
        __syncthreads();
        float a = bse1[d];
#pragma unroll 8
        for (int k = 0; k < 64; k++) a = fmaf(xs[nl * 64 + k], Wse1[k * 64 + d], a);
        hs[nl * 64 + d] = fmaxf(a, 0.f);
        __syncthreads();
        float o = bse2[d];
#pragma unroll 8
        for (int k = 0; k < 64; k++) o = fmaf(hs[nl * 64 + k], Wse2[k * 64 + d], o);
        g_se[n * 64 + d] = o;
    } else {
        // ---- temporal embedding: 4 rows per block ----
        float* hs = sh;
        int rl = t >> 6, d = t & 63;
        int row = (bid - 305) * 4 + rl;
        int b = row / Pk, p = row - b * Pk;
        int base = (b * (Pk + Qk) + p) * 2;
        int t0 = TE[base], t1 = TE[base + 1];
        float a = Wte1[t0 * 64 + d] + Wte1[(7 + t1) * 64 + d] + bte1[d];
        hs[rl * 64 + d] = fmaxf(a, 0.f);
        __syncthreads();
        float o = bte2[d];
#pragma unroll 8
        for (int k = 0; k < 64; k++) o = fmaf(hs[rl * 64 + k], Wte2[k * 64 + d], o);
        g_te[row * 64 + d] = o;
    }
}

// ---------------- FC_in: closed-form affine -> fp16 frag output ----------------
__global__ __launch_bounds__(256) void k_fc_in_h(const float* __restrict__ X) {
    __shared__ float sA[65 * 64], sB[65 * 64], sTs[64], sTe[64];
    __shared__ float sXs[1024];
    __shared__ int sSeg[1024];
    int tid = threadIdx.x;
    int bp = blockIdx.x;
    {
        const float4* a = (const float4*)g_alpha;
        const float4* b = (const float4*)g_beta;
        float4* da = (float4*)sA;
        float4* db = (float4*)sB;
        for (int i = tid; i < 1040; i += 256) { da[i] = a[i]; db[i] = b[i]; }
    }
    if (tid < 64) { sTs[tid] = g_ts[tid]; sTe[tid] = g_te[bp * 64 + tid]; }
    __syncthreads();
    for (int i = tid; i < 1024; i += 256) {
        float x = X[(size_t)bp * 1024 + i];
        sXs[i] = x;
        int sg = 0;
#pragma unroll 16
        for (int k = 0; k < 64; k++) sg += (sTs[k] < x);
        sSeg[i] = sg;
    }
    __syncthreads();
#pragma unroll 4
    for (int it = 0; it < 32; it++) {
        int sl = it * 256 + tid;
        int nt = sl >> 9, r9 = sl & 511;
        int mt = r9 >> 7, kt = (r9 >> 5) & 3, s = r9 & 31;
        int g = s >> 2, tig = s & 3;
        int n0 = nt * 64 + 16 * mt + g, n1 = n0 + 8;
        int c0 = 16 * kt + 2 * tig, c1 = c0 + 8;
        float x0 = sXs[n0], x1 = sXs[n1];
        int s0 = sSeg[n0] * 64, s1 = sSeg[n1] * 64;
        float2 a00 = *(const float2*)&sA[s0 + c0], b00 = *(const float2*)&sB[s0 + c0];
        float2 a01 = *(const float2*)&sA[s0 + c1], b01 = *(const float2*)&sB[s0 + c1];
        float2 a10 = *(const float2*)&sA[s1 + c0], b10 = *(const float2*)&sB[s1 + c0];
        float2 a11 = *(const float2*)&sA[s1 + c1], b11 = *(const float2*)&sB[s1 + c1];
        float2 se00 = *(const float2*)&g_se[n0 * 64 + c0];
        float2 se01 = *(const float2*)&g_se[n0 * 64 + c1];
        float2 se10 = *(const float2*)&g_se[n1 * 64 + c0];
        float2 se11 = *(const float2*)&g_se[n1 * 64 + c1];
        float2 te0 = *(const float2*)&sTe[c0];
        float2 te1 = *(const float2*)&sTe[c1];
        uint32 u0 = packh2(fmaf(x0, a00.x, b00.x) + se00.x + te0.x,
                           fmaf(x0, a00.y, b00.y) + se00.y + te0.y);
        uint32 u1 = packh2(fmaf(x1, a10.x, b10.x) + se10.x + te0.x,
                           fmaf(x1, a10.y, b10.y) + se10.y + te0.y);
        uint32 u2 = packh2(fmaf(x0, a01.x, b01.x) + se01.x + te1.x,
                           fmaf(x0, a01.y, b01.y) + se01.y + te1.y);
        uint32 u3 = packh2(fmaf(x1, a11.x, b11.x) + se11.x + te1.x,
                           fmaf(x1, a11.y, b11.y) + se11.y + te1.y);
        *(uint4*)&g_XeH[(size_t)(bp * 16 + nt) * 2048 + (mt * 4 + kt) * 128 + s * 4] =
            make_uint4(u0, u1, u2, u3);
    }
}

// ---------------- GRU phase helpers (256-thr config, cached A-input frags) ----------------
__device__ __forceinline__ void loadA2(const uint32* __restrict__ buf,
                                       uint4 (&f)[2][4], int lane, int mp) {
#pragma unroll
    for (int mt = 0; mt < 2; mt++)
#pragma unroll
        for (int kt = 0; kt < 4; kt++)
            f[mt][kt] = *(const uint4*)&buf[((2 * mp + mt) * 4 + kt) * 128 + lane * 4];
}

__device__ __forceinline__ void phaseA_c(
        const uint4 (&ax)[2][4], const uint32* __restrict__ Sf,
        const uint32* __restrict__ gWl,
        float (&aR)[2][2][4], float (&aU)[2][2][4], int lane, int mp, int nq) {
#pragma unroll
    for (int mt = 0; mt < 2; mt++)
#pragma unroll
        for (int nt = 0; nt < 2; nt++)
#pragma unroll
            for (int v = 0; v < 4; v++) { aR[mt][nt][v] = 0.f; aU[mt][nt][v] = 0.f; }
#pragma unroll
    for (int ktp = 0; ktp < 2; ktp++) {
        uint4 bRx[2], bRs[2], bUx[2], bUs[2];
#pragma unroll
        for (int nt = 0; nt < 2; nt++) {
            int nr = 2 * nq + nt, nu = nr + 8;
            bRx[nt] = *(const uint4*)&gWl[(nr * 2 + ktp) * 128 + lane * 4];
            bRs[nt] = *(const uint4*)&gWl[((16 + nr) * 2 + ktp) * 128 + lane * 4];
            bUx[nt] = *(const uint4*)&gWl[(nu * 2 + ktp) * 128 + lane * 4];
            bUs[nt] = *(const uint4*)&gWl[((16 + nu) * 2 + ktp) * 128 + lane * 4];
        }
#pragma unroll
        for (int k2 = 0; k2 < 2; k2++) {
            int kt = 2 * ktp + k2;
            uint4 as2[2];
#pragma unroll
            for (int mt = 0; mt < 2; mt++)
                as2[mt] = *(const uint4*)&Sf[((2 * mp + mt) * 4 + kt) * 128 + lane * 4];
#pragma unroll
            for (int nt = 0; nt < 2; nt++) {
                uint32 rx0 = k2 ? bRx[nt].z : bRx[nt].x, rx1 = k2 ? bRx[nt].w : bRx[nt].y;
                uint32 rs0 = k2 ? bRs[nt].z : bRs[nt].x, rs1 = k2 ? bRs[nt].w : bRs[nt].y;
                uint32 ux0 = k2 ? bUx[nt].z : bUx[nt].x, ux1 = k2 ? bUx[nt].w : bUx[nt].y;
                uint32 us0 = k2 ? bUs[nt].z : bUs[nt].x, us1 = k2 ? bUs[nt].w : bUs[nt].y;
#pragma unroll
                for (int mt = 0; mt < 2; mt++) {
                    mma_f16(aR[mt][nt], ax[mt][kt], rx0, rx1);
                    mma_f16(aR[mt][nt], as2[mt], rs0, rs1);
                    mma_f16(aU[mt][nt], ax[mt][kt], ux0, ux1);
                    mma_f16(aU[mt][nt], as2[mt], us0, us1);
                }
            }
        }
    }
}

__device__ __forceinline__ void epiA(
        const float (&aR)[2][2][4], const float (&aU)[2][2][4],
        const float (&bgr)[2][2], const float (&bgu)[2][2],
        const float (&sr)[2][2][4], float (&uv)[2][2][4],
        uint32* __restrict__ Rf, int mp, int nq, int g, int tig) {
#pragma unroll
    for (int mt = 0; mt < 2; mt++) {
        uint32 o[4];
#pragma unroll
        for (int nt = 0; nt < 2; nt++) {
            float r0 = sigm_a(aR[mt][nt][0] + bgr[nt][0]);
            float r1 = sigm_a(aR[mt][nt][1] + bgr[nt][1]);
            float r2 = sigm_a(aR[mt][nt][2] + bgr[nt][0]);
            float r3 = sigm_a(aR[mt][nt][3] + bgr[nt][1]);
            uv[mt][nt][0] = sigm_a(aU[mt][nt][0] + bgu[nt][0]);
            uv[mt][nt][1] = sigm_a(aU[mt][nt][1] + bgu[nt][1]);
            uv[mt][nt][2] = sigm_a(aU[mt][nt][2] + bgu[nt][0]);
            uv[mt][nt][3] = sigm_a(aU[mt][nt][3] + bgu[nt][1]);
            o[2 * nt + 0] = packh2(r0 * sr[mt][nt][0], r1 * sr[mt][nt][1]);
            o[2 * nt + 1] = packh2(r2 * sr[mt][nt][2], r3 * sr[mt][nt][3]);
        }
        *(uint4*)&Rf[((2 * mp + mt) * 4 + nq) * 128 + (4 * g + tig) * 4] =
            make_uint4(o[0], o[1], o[2], o[3]);
    }
}

__device__ __forceinline__ void phaseB_c(
        const uint4 (&ax)[2][4], const uint32* __restrict__ Rf,
        const uint32* __restrict__ cWl, float (&aC)[2][2][4], int lane, int mp, int nq) {
#pragma unroll
    for (int mt = 0; mt < 2; mt++)
#pragma unroll
        for (int nt = 0; nt < 2; nt++)
#pragma unroll
            for (int v = 0; v < 4; v++) aC[mt][nt][v] = 0.f;
#pragma unroll
    for (int ktp = 0; ktp < 2; ktp++) {
        uint4 bCx[2], bCs[2];
#pragma unroll
        for (int nt = 0; nt < 2; nt++) {
            int nc = 2 * nq + nt;
            bCx[nt] = *(const uint4*)&cWl[(nc * 2 + ktp) * 128 + lane * 4];
            bCs[nt] = *(const uint4*)&cWl[((8 + nc) * 2 + ktp) * 128 + lane * 4];
        }
#pragma unroll
        for (int k2 = 0; k2 < 2; k2++) {
            int kt = 2 * ktp + k2;
            uint4 ar[2];
#pragma unroll
            for (int mt = 0; mt < 2; mt++)
                ar[mt] = *(const uint4*)&Rf[((2 * mp + mt) * 4 + kt) * 128 + lane * 4];
#pragma unroll
            for (int nt = 0; nt < 2; nt++) {
                uint32 x0 = k2 ? bCx[nt].z : bCx[nt].x, x1 = k2 ? bCx[nt].w : bCx[nt].y;
                uint32 s0 = k2 ? bCs[nt].z : bCs[nt].x, s1 = k2 ? bCs[nt].w : bCs[nt].y;
#pragma unroll
                for (int mt = 0; mt < 2; mt++) {
                    mma_f16(aC[mt][nt], ax[mt][kt], x0, x1);
                    mma_f16(aC[mt][nt], ar[mt], s0, s1);
                }
            }
        }
    }
}

__device__ __forceinline__ void epiB(
        const float (&aC)[2][2][4], const float (&bcc)[2][2],
        const float (&uv)[2][2][4], float (&sr)[2][2][4],
        uint32* __restrict__ Sf, int mp, int nq, int g, int tig) {
#pragma unroll
    for (int mt = 0; mt < 2; mt++) {
        uint32 o[4];
#pragma unroll
        for (int nt = 0; nt < 2; nt++) {
            float c0 = tanh_fast(aC[mt][nt][0] + bcc[nt][0]);
            float c1 = tanh_fast(aC[mt][nt][1] + bcc[nt][1]);
            float c2 = tanh_fast(aC[mt][nt][2] + bcc[nt][0]);
            float c3 = tanh_fast(aC[mt][nt][3] + bcc[nt][1]);
            float n0 = fmaf(uv[mt][nt][0], sr[mt][nt][0] - c0, c0);
            float n1 = fmaf(uv[mt][nt][1], sr[mt][nt][1] - c1, c1);
            float n2 = fmaf(uv[mt][nt][2], sr[mt][nt][2] - c2, c2);
            float n3 = fmaf(uv[mt][nt][3], sr[mt][nt][3] - c3, c3);
            sr[mt][nt][0] = n0; sr[mt][nt][1] = n1;
            sr[mt][nt][2] = n2; sr[mt][nt][3] = n3;
            o[2 * nt + 0] = packh2(n0, n1);
            o[2 * nt + 1] = packh2(n2, n3);
        }
        *(uint4*)&Sf[((2 * mp + mt) * 4 + nq) * 128 + (4 * g + tig) * 4] =
            make_uint4(o[0], o[1], o[2], o[3]);
    }
}

// ---------------- fused 2-layer DCGRU scan + FC_out tail ----------------
// smem (u32): gW0 8192 | gW1 8192 | cW0 4096 | cW1 4096 | Xf 2x2048 | S1f 2x2048 |
//             S2f 2048 | Rf1 2048 | Rf2 2048 | sb 384f | oW1 4096f | oW2 768f | ob 80f
__global__ __launch_bounds__(256, 1) void k_scan(
        const float* __restrict__ bg1_, const float* __restrict__ bc1_,
        const float* __restrict__ bg2_, const float* __restrict__ bc2_,
        const float* __restrict__ Wo1, const float* __restrict__ bo1,
        const float* __restrict__ Wo2, const float* __restrict__ bo2,
        float* __restrict__ out) {
    extern __shared__ uint32 smu[];
    uint32* gW0 = smu;
    uint32* gW1 = smu + 8192;
    uint32* cW0 = smu + 16384;
    uint32* cW1 = smu + 20480;
    uint32* Xf  = smu + 24576;
    uint32* S1f = smu + 28672;
    uint32* S2f = smu + 32768;
    uint32* Rf1 = smu + 34816;
    uint32* Rf2 = smu + 36864;
    float*  sb  = (float*)(smu + 38912);
    float*  oW1 = (float*)(smu + 39296);
    float*  oW2 = (float*)(smu + 43392);
    float*  ob1 = (float*)(smu + 44160);
    float*  ob2 = (float*)(smu + 44224);

    int tid = threadIdx.x;
    {
        const uint4* s0 = (const uint4*)g_gWh[0];
        const uint4* s1 = (const uint4*)g_gWh[1];
        uint4* d0 = (uint4*)gW0; uint4* d1 = (uint4*)gW1;
        for (int i = tid; i < 2048; i += 256) { d0[i] = s0[i]; d1[i] = s1[i]; }
        const uint4* c0 = (const uint4*)g_cWh[0];
        const uint4* c1 = (const uint4*)g_cWh[1];
        uint4* e0 = (uint4*)cW0; uint4* e1 = (uint4*)cW1;
        for (int i = tid; i < 1024; i += 256) { e0[i] = c0[i]; e1[i] = c1[i]; }
        for (int i = tid; i < 4096; i += 256) oW1[i] = Wo1[i];
        for (int i = tid; i < 768; i += 256) oW2[i] = Wo2[i];
        if (tid < 64) ob1[tid] = bo1[tid];
        if (tid < 12) ob2[tid] = bo2[tid];
    }
    if (tid < 128) { sb[tid] = bg1_[tid]; sb[128 + tid] = bg2_[tid]; }
    if (tid < 64)  { sb[256 + tid] = bc1_[tid]; sb[320 + tid] = bc2_[tid]; }
    {
        uint4 z = make_uint4(0, 0, 0, 0);
        uint4* z1 = (uint4*)S1f; uint4* z2 = (uint4*)S2f;
        for (int i = tid; i < 1024; i += 256) z1[i] = z;
        for (int i = tid; i < 512; i += 256) z2[i] = z;
    }
    int row0 = blockIdx.x * 64;
    int b = row0 >> 10, ntb = (row0 >> 6) & 15;
    {   // x(0) -> Xf[0], x(1) -> Xf[1]
        const uint4* s0 = (const uint4*)&g_XeH[(size_t)(b * Pk * 16 + ntb) * 2048];
        const uint4* s1 = (const uint4*)&g_XeH[(size_t)((b * Pk + 1) * 16 + ntb) * 2048];
        uint4* d0 = (uint4*)Xf;
        uint4* d1 = (uint4*)(Xf + 2048);
        d0[tid] = s0[tid]; d0[tid + 256] = s0[tid + 256];
        d1[tid] = s1[tid]; d1[tid + 256] = s1[tid + 256];
    }
    __syncthreads();

    int lane = tid & 31, w = tid >> 5;
    int mp = w & 1, nq = w >> 1, g = lane >> 2, tig = lane & 3;

    float bgr1[2][2], bgu1[2][2], bcc1[2][2];
    float bgr2[2][2], bgu2[2][2], bcc2[2][2];
#pragma unroll
    for (int nt = 0; nt < 2; nt++) {
        int j = 16 * nq + 8 * nt + 2 * tig;
        bgr1[nt][0] = sb[j];           bgr1[nt][1] = sb[j + 1];
        bgu1[nt][0] = sb[64 + j];      bgu1[nt][1] = sb[64 + j + 1];
        bgr2[nt][0] = sb[128 + j];     bgr2[nt][1] = sb[128 + j + 1];
        bgu2[nt][0] = sb[192 + j];     bgu2[nt][1] = sb[192 + j + 1];
        bcc1[nt][0] = sb[256 + j];     bcc1[nt][1] = sb[256 + j + 1];
        bcc2[nt][0] = sb[320 + j];     bcc2[nt][1] = sb[320 + j + 1];
    }
    float s1r[2][2][4], s2r[2][2][4];
#pragma unroll
    for (int mt = 0; mt < 2; mt++)
#pragma unroll
        for (int nt = 0; nt < 2; nt++)
#pragma unroll
            for (int v = 0; v < 4; v++) { s1r[mt][nt][v] = 0.f; s2r[mt][nt][v] = 0.f; }

    float uv1[2][2][4], uv2[2][2][4];
    uint4 xf1[2][4], xf2[2][4];

    // ---- standalone L1 at t=0 ----
    loadA2(Xf, xf1, lane, mp);
    {
        float aR[2][2][4], aU[2][2][4];
        phaseA_c(xf1, S1f + 2048, gW0, aR, aU, lane, mp, nq);
        epiA(aR, aU, bgr1, bgu1, s1r, uv1, Rf1, mp, nq, g, tig);
    }
    __syncthreads();
    {
        float aC[2][2][4];
        phaseB_c(xf1, Rf1, cW0, aC, lane, mp, nq);
        epiB(aC, bcc1, uv1, s1r, S1f, mp, nq, g, tig);
    }
    __syncthreads();

    // ---- fused supersteps: L1 at t=k+1 with L2 at t=k ----
    for (int k = 0; k <= 10; k++) {
        int p = k & 1;
        uint32* Xc  = Xf + ((k + 1) & 1) * 2048;
        uint32* S1c = S1f + p * 2048;
        uint32* S1n = S1f + (p ^ 1) * 2048;
        loadA2(Xc, xf1, lane, mp);
        loadA2(S1c, xf2, lane, mp);
        if (k + 2 < Pk) {
            const uint4* s = (const uint4*)&g_XeH[(size_t)((b * Pk + k + 2) * 16 + ntb) * 2048];
            uint4* dst = (uint4*)(Xf + (k & 1) * 2048);
            uint32 sa = (uint32)__cvta_generic_to_shared(&dst[tid]);
            asm volatile("cp.async.cg.shared.global [%0], [%1], 16;"
                         :: "r"(sa), "l"(s + tid) : "memory");
            asm volatile("cp.async.cg.shared.global [%0], [%1], 16;"
                         :: "r"(sa + 4096), "l"(s + tid + 256) : "memory");
            asm volatile("cp.async.commit_group;" ::: "memory");
        }
        {
            float aR[2][2][4], aU[2][2][4];
            phaseA_c(xf1, S1c, gW0, aR, aU, lane, mp, nq);
            epiA(aR, aU, bgr1, bgu1, s1r, uv1, Rf1, mp, nq, g, tig);
        }
        {
            float aR[2][2][4], aU[2][2][4];
            phaseA_c(xf2, S2f, gW1, aR, aU, lane, mp, nq);
            epiA(aR, aU, bgr2, bgu2, s2r, uv2, Rf2, mp, nq, g, tig);
        }
        __syncthreads();
        {
            float aC[2][2][4];
            phaseB_c(xf1, Rf1, cW0, aC, lane, mp, nq);
            epiB(aC, bcc1, uv1, s1r, S1n, mp, nq, g, tig);
        }
        {
            float aC[2][2][4];
            phaseB_c(xf2, Rf2, cW1, aC, lane, mp, nq);
            epiB(aC, bcc2, uv2, s2r, S2f, mp, nq, g, tig);
        }
        asm volatile("cp.async.wait_group 0;" ::: "memory");
        __syncthreads();
    }

    // ---- standalone L2 at t=11: input S1(11) in S1f[1] ----
    loadA2(S1f + 2048, xf2, lane, mp);
    {
        float aR[2][2][4], aU[2][2][4];
        phaseA_c(xf2, S2f, gW1, aR, aU, lane, mp, nq);
        epiA(aR, aU, bgr2, bgu2, s2r, uv2, Rf2, mp, nq, g, tig);
    }
    __syncthreads();
    {
        float aC[2][2][4];
        phaseB_c(xf2, Rf2, cW1, aC, lane, mp, nq);
        epiB(aC, bcc2, uv2, s2r, S2f, mp, nq, g, tig);
    }

    // ---- FC_out tail: h = s2r (exact fp32 in regs) ----
    __syncthreads();
    float* hS = (float*)gW0;   // 64 x 68 (weights no longer needed)
    float* sH = (float*)gW1;   // 64 x 65
#pragma unroll
    for (int mt = 0; mt < 2; mt++) {
#pragma unroll
        for (int nt = 0; nt < 2; nt++) {
            int j = 16 * nq + 8 * nt + 2 * tig;
            int rl = (2 * mp + mt) * 16 + g;
            *(float2*)&hS[rl * 68 + j]       = make_float2(s2r[mt][nt][0], s2r[mt][nt][1]);
            *(float2*)&hS[(rl + 8) * 68 + j] = make_float2(s2r[mt][nt][2], s2r[mt][nt][3]);
        }
    }
    __syncthreads();
    {
        int c0 = lane * 2;
        float acc[8][2];
#pragma unroll
        for (int ri = 0; ri < 8; ri++) { acc[ri][0] = 0.f; acc[ri][1] = 0.f; }
#pragma unroll 8
        for (int k = 0; k < 64; k++) {
            float2 wv = *(const float2*)&oW1[k * 64 + c0];
#pragma unroll
            for (int ri = 0; ri < 8; ri++) {
                float h = hS[(w + ri * 8) * 68 + k];
                acc[ri][0] = fmaf(h, wv.x, acc[ri][0]);
                acc[ri][1] = fmaf(h, wv.y, acc[ri][1]);
            }
        }
#pragma unroll
        for (int ri = 0; ri < 8; ri++) {
            int i = w + ri * 8;
            sH[i * 65 + c0]     = fmaxf(acc[ri][0] + ob1[c0], 0.f);
            sH[i * 65 + c0 + 1] = fmaxf(acc[ri][1] + ob1[c0 + 1], 0.f);
        }
    }
    __syncthreads();
    {
        int i = tid >> 2;
        int q0 = (tid & 3) * 3;
        float a0 = ob2[q0], a1 = ob2[q0 + 1], a2 = ob2[q0 + 2];
#pragma unroll 8
        for (int k = 0; k < 64; k++) {
            float h = sH[i * 65 + k];
            a0 = fmaf(h, oW2[k * 12 + q0],     a0);
            a1 = fmaf(h, oW2[k * 12 + q0 + 1], a1);
            a2 = fmaf(h, oW2[k * 12 + q0 + 2], a2);
        }
        int r = row0 + i, bb = r >> 10, n = r & 1023;
        out[(((size_t)bb * Qk + q0)     << 10) + n] = a0;
        out[(((size_t)bb * Qk + q0 + 1) << 10) + n] = a1;
        out[(((size_t)bb * Qk + q0 + 2) << 10) + n] = a2;
    }
}

// ---------------- launch ----------------
extern "C" void kernel_launch(void* const* d_in, const int* in_sizes, int n_in,
                              void* d_out, int out_size) {
    const float* X     = (const float*)d_in[0];
    const float* SE    = (const float*)d_in[3];
    const float* W_se1 = (const float*)d_in[4];  const float* b_se1 = (const float*)d_in[5];
    const float* W_se2 = (const float*)d_in[6];  const float* b_se2 = (const float*)d_in[7];
    const float* W_te1 = (const float*)d_in[8];  const float* b_te1 = (const float*)d_in[9];
    const float* W_te2 = (const float*)d_in[10]; const float* b_te2 = (const float*)d_in[11];
    const float* W_in1 = (const float*)d_in[12]; const float* b_in1 = (const float*)d_in[13];
    const float* W_in2 = (const float*)d_in[14]; const float* b_in2 = (const float*)d_in[15];
    const float* Wg1   = (const float*)d_in[16]; const float* bg1   = (const float*)d_in[17];
    const float* Wc1   = (const float*)d_in[18]; const float* bc1   = (const float*)d_in[19];
    const float* Wg2   = (const float*)d_in[20]; const float* bg2   = (const float*)d_in[21];
    const float* Wc2   = (const float*)d_in[22]; const float* bc2   = (const float*)d_in[23];
    const float* W_o1  = (const float*)d_in[24]; const float* b_o1  = (const float*)d_in[25];
    const float* W_o2  = (const float*)d_in[26]; const float* b_o2  = (const float*)d_in[27];
    const int*   TE    = (const int*)d_in[28];
    float* out = (float*)d_out;

    const size_t scan_smem = (size_t)44240 * 4;   // 176,960 B
    cudaFuncSetAttribute(k_scan, cudaFuncAttributeMaxDynamicSharedMemorySize,
                         (int)scan_smem);

    k_setup<<<497, 256>>>(Wg1, Wc1, Wg2, Wc2,
                          W_in1, b_in1, W_in2, b_in2,
                          SE, W_se1, b_se1, W_se2, b_se2,
                          TE, W_te1, b_te1, W_te2, b_te2);
    k_fc_in_h<<<Bk * Pk, 256>>>(X);
    k_scan<<<Bk * Nk / 64, 256, scan_smem>>>(bg1, bc1, bg2, bc2,
                                             W_o1, b_o1, W_o2, b_o2, out);
}

// round 15
// speedup vs baseline: 1.3062x; 1.1848x over previous
#include <cuda_runtime.h>
#include <cuda_fp16.h>

#define Bk 64
#define Pk 12
#define Qk 12
#define Nk 1024
#define Dk 64

typedef unsigned int uint32;

__device__ __forceinline__ uint32 packh2(float a, float b) {
    __half2 h = __floats2half2_rn(a, b);
    return *(uint32*)&h;
}
__device__ __forceinline__ void mma_f16(float* d, uint4 a, uint32 b0, uint32 b1) {
    asm("mma.sync.aligned.m16n8k16.row.col.f32.f16.f16.f32 "
        "{%0,%1,%2,%3},{%4,%5,%6,%7},{%8,%9},{%0,%1,%2,%3};"
        : "+f"(d[0]), "+f"(d[1]), "+f"(d[2]), "+f"(d[3])
        : "r"(a.x), "r"(a.y), "r"(a.z), "r"(a.w), "r"(b0), "r"(b1));
}
__device__ __forceinline__ float tanh_a(float z) {
    float y;
    asm("tanh.approx.f32 %0, %1;" : "=f"(y) : "f"(z));
    return y;
}
__device__ __forceinline__ float sigm_a(float z) {
    return fmaf(0.5f, tanh_a(0.5f * z), 0.5f);
}
__device__ __forceinline__ float tanh_fast(float z) {
    z = fminf(fmaxf(z, -15.f), 15.f);
    float e = __expf(-2.f * z);
    return __fdividef(1.f - e, 1.f + e);
}

// ---------------- scratch ----------------
__device__ float g_se[Nk * Dk];
__device__ float g_te[Bk * Pk * Dk];
__device__ uint32 g_XeH[(size_t)Bk * Pk * 16 * 2048];
__device__ uint32 g_gWh[2][8192];
__device__ uint32 g_cWh[2][4096];
__device__ float g_alpha[65 * 64];
__device__ float g_beta[65 * 64];
__device__ float g_ts[64];

// ---------------- fused setup ----------------
// bid 0..47   : weight folding + fp16 frag packing
// bid 48..112 : fc_in piecewise-linear table, one segment per block
// bid 113..368: spatial embedding (4 rows/block)
// bid 369..560: temporal embedding (4 rows/block)
__global__ __launch_bounds__(256) void k_setup(
        const float* __restrict__ Wg1, const float* __restrict__ Wc1,
        const float* __restrict__ Wg2, const float* __restrict__ Wc2,
        const float* __restrict__ Wi1, const float* __restrict__ bi1,
        const float* __restrict__ Wi2, const float* __restrict__ bi2,
        const float* __restrict__ SE,
        const float* __restrict__ Wse1, const float* __restrict__ bse1,
        const float* __restrict__ Wse2, const float* __restrict__ bse2,
        const int* __restrict__ TE,
        const float* __restrict__ Wte1, const float* __restrict__ bte1,
        const float* __restrict__ Wte2, const float* __restrict__ bte2) {
    __shared__ float sh[512];
    __shared__ int shi[64];
    int bid = blockIdx.x;
    int t = threadIdx.x;
    if (bid < 48) {
        // ---- weight folding + fp16 frag packing ----
        int tid = bid * 256 + t;
        int stride = 48 * 256;
        for (int i = tid; i < 16384; i += stride) {
            int v = i & 3, lane = (i >> 2) & 31, ktp = (i >> 7) & 1;
            int n8 = (i >> 8) & 15, pt = (i >> 12) & 1, l = (i >> 13) & 1;
            int kt = 2 * ktp + (v >> 1), reg = v & 1;
            int g = lane >> 2, tig = lane & 3;
            int k0 = kt * 16 + 2 * tig + 8 * reg;
            int n = n8 * 8 + g;
            const float* W = l ? Wg2 : Wg1;
            int r0 = pt * 64;
            float f0 = W[(r0 + k0) * 128 + n] + W[(r0 + 128 + k0) * 128 + n];
            float f1 = W[(r0 + k0 + 1) * 128 + n] + W[(r0 + 129 + k0) * 128 + n];
            g_gWh[l][((pt * 16 + n8) * 2 + ktp) * 128 + lane * 4 + v] = packh2(f0, f1);
        }
        for (int i = tid; i < 8192; i += stride) {
            int v = i & 3, lane = (i >> 2) & 31, ktp = (i >> 7) & 1;
            int n8 = (i >> 8) & 7, pt = (i >> 11) & 1, l = (i >> 12) & 1;
            int kt = 2 * ktp + (v >> 1), reg = v & 1;
            int g = lane >> 2, tig = lane & 3;
            int k0 = kt * 16 + 2 * tig + 8 * reg;
            int n = n8 * 8 + g;
            const float* W = l ? Wc2 : Wc1;
            int r0 = pt * 64;
            float f0 = W[(r0 + k0) * 64 + n] + W[(r0 + 128 + k0) * 64 + n];
            float f1 = W[(r0 + k0 + 1) * 64 + n] + W[(r0 + 129 + k0) * 64 + n];
            g_cWh[l][((pt * 8 + n8) * 2 + ktp) * 128 + lane * 4 + v] = packh2(f0, f1);
        }
    } else if (bid < 113) {
        // ---- fc_in piecewise-linear table: segment s = bid - 48 ----
        int s = bid - 48;
        float* w1s = sh;
        float* b1s = sh + 64;
        float* tsr = sh + 128;
        if (t < 64) { w1s[t] = Wi1[t]; b1s[t] = bi1[t]; }
        __syncthreads();
        if (t < 64) {
            float w = w1s[t];
            tsr[t] = (w != 0.f) ? (-b1s[t] / w) : __int_as_float(0x7f800000);
        }
        __syncthreads();
        if (t < 64) {
            float tv = tsr[t];
            int r = 0;
            for (int d = 0; d < 64; d++) {
                float td = tsr[d];
                r += (td < tv) || (td == tv && d < t);
            }
            shi[t] = r;
            if (s == 0) g_ts[r] = tv;
        }
        __syncthreads();
        if (t < 64) {
            int c = t;
            float a = 0.f, bt = 0.f;
            for (int d = 0; d < 64; d++) {
                float w = w1s[d];
                bool act = (w > 0.f) ? (shi[d] < s)
                         : ((w < 0.f) ? (shi[d] >= s) : (b1s[d] > 0.f));
                if (act) {
                    float w2 = Wi2[d * 64 + c];
                    a = fmaf(w, w2, a);
                    bt = fmaf(b1s[d], w2, bt);
                }
            }
            g_alpha[s * 64 + c] = a;
            g_beta[s * 64 + c] = bt + bi2[c];
        }
    } else if (bid < 369) {
        // ---- spatial embedding: 4 n-rows per block ----
        float* xs = sh;
        float* hs = sh + 256;
        int nl = t >> 6, d = t & 63;
        int n = (bid - 113) * 4 + nl;
        xs[nl * 64 + d] = SE[n * 64 + d];
        __syncthreads();
        float a = bse1[d];
#pragma unroll 8
        for (int k = 0; k < 64; k++) a = fmaf(xs[nl * 64 + k], Wse1[k * 64 + d], a);
        hs[nl * 64 + d] = fmaxf(a, 0.f);
        __syncthreads();
        float o = bse2[d];
#pragma unroll 8
        for (int k = 0; k < 64; k++) o = fmaf(hs[nl * 64 + k], Wse2[k * 64 + d], o);
        g_se[n * 64 + d] = o;
    } else {
        // ---- temporal embedding: 4 rows per block ----
        float* hs = sh;
        int rl = t >> 6, d = t & 63;
        int row = (bid - 369) * 4 + rl;
        int b = row / Pk, p = row - b * Pk;
        int base = (b * (Pk + Qk) + p) * 2;
        int t0 = TE[base], t1 = TE[base + 1];
        float a = Wte1[t0 * 64 + d] + Wte1[(7 + t1) * 64 + d] + bte1[d];
        hs[rl * 64 + d] = fmaxf(a, 0.f);
        __syncthreads();
        float o = bte2[d];
#pragma unroll 8
        for (int k = 0; k < 64; k++) o = fmaf(hs[rl * 64 + k], Wte2[k * 64 + d], o);
        g_te[row * 64 + d] = o;
    }
}

// ---------------- FC_in: closed-form affine -> fp16 frag output ----------------
__global__ __launch_bounds__(256) void k_fc_in_h(const float* __restrict__ X) {
    __shared__ float sA[65 * 64], sB[65 * 64], sTs[64], sTe[64];
    __shared__ float sXs[1024];
    __shared__ int sSeg[1024];
    int tid = threadIdx.x;
    int bp = blockIdx.x;
    {
        const float4* a = (const float4*)g_alpha;
        const float4* b = (const float4*)g_beta;
        float4* da = (float4*)sA;
        float4* db = (float4*)sB;
        for (int i = tid; i < 1040; i += 256) { da[i] = a[i]; db[i] = b[i]; }
    }
    if (tid < 64) { sTs[tid] = g_ts[tid]; sTe[tid] = g_te[bp * 64 + tid]; }
    __syncthreads();
    for (int i = tid; i < 1024; i += 256) {
        float x = X[(size_t)bp * 1024 + i];
        sXs[i] = x;
        int sg = 0;
#pragma unroll 16
        for (int k = 0; k < 64; k++) sg += (sTs[k] < x);
        sSeg[i] = sg;
    }
    __syncthreads();
#pragma unroll 4
    for (int it = 0; it < 32; it++) {
        int sl = it * 256 + tid;
        int nt = sl >> 9, r9 = sl & 511;
        int mt = r9 >> 7, kt = (r9 >> 5) & 3, s = r9 & 31;
        int g = s >> 2, tig = s & 3;
        int n0 = nt * 64 + 16 * mt + g, n1 = n0 + 8;
        int c0 = 16 * kt + 2 * tig, c1 = c0 + 8;
        float x0 = sXs[n0], x1 = sXs[n1];
        int s0 = sSeg[n0] * 64, s1 = sSeg[n1] * 64;
        float2 a00 = *(const float2*)&sA[s0 + c0], b00 = *(const float2*)&sB[s0 + c0];
        float2 a01 = *(const float2*)&sA[s0 + c1], b01 = *(const float2*)&sB[s0 + c1];
        float2 a10 = *(const float2*)&sA[s1 + c0], b10 = *(const float2*)&sB[s1 + c0];
        float2 a11 = *(const float2*)&sA[s1 + c1], b11 = *(const float2*)&sB[s1 + c1];
        float2 se00 = *(const float2*)&g_se[n0 * 64 + c0];
        float2 se01 = *(const float2*)&g_se[n0 * 64 + c1];
        float2 se10 = *(const float2*)&g_se[n1 * 64 + c0];
        float2 se11 = *(const float2*)&g_se[n1 * 64 + c1];
        float2 te0 = *(const float2*)&sTe[c0];
        float2 te1 = *(const float2*)&sTe[c1];
        uint32 u0 = packh2(fmaf(x0, a00.x, b00.x) + se00.x + te0.x,
                           fmaf(x0, a00.y, b00.y) + se00.y + te0.y);
        uint32 u1 = packh2(fmaf(x1, a10.x, b10.x) + se10.x + te0.x,
                           fmaf(x1, a10.y, b10.y) + se10.y + te0.y);
        uint32 u2 = packh2(fmaf(x0, a01.x, b01.x) + se01.x + te1.x,
                           fmaf(x0, a01.y, b01.y) + se01.y + te1.y);
        uint32 u3 = packh2(fmaf(x1, a11.x, b11.x) + se11.x + te1.x,
                           fmaf(x1, a11.y, b11.y) + se11.y + te1.y);
        *(uint4*)&g_XeH[(size_t)(bp * 16 + nt) * 2048 + (mt * 4 + kt) * 128 + s * 4] =
            make_uint4(u0, u1, u2, u3);
    }
}

// ---------------- GRU phase helpers (256-thr config, cached A-input frags) ----------------
__device__ __forceinline__ void loadA2(const uint32* __restrict__ buf,
                                       uint4 (&f)[2][4], int lane, int mp) {
#pragma unroll
    for (int mt = 0; mt < 2; mt++)
#pragma unroll
        for (int kt = 0; kt < 4; kt++)
            f[mt][kt] = *(const uint4*)&buf[((2 * mp + mt) * 4 + kt) * 128 + lane * 4];
}

__device__ __forceinline__ void phaseA_c(
        const uint4 (&ax)[2][4], const uint32* __restrict__ Sf,
        const uint32* __restrict__ gWl,
        float (&aR)[2][2][4], float (&aU)[2][2][4], int lane, int mp, int nq) {
#pragma unroll
    for (int mt = 0; mt < 2; mt++)
#pragma unroll
        for (int nt = 0; nt < 2; nt++)
#pragma unroll
            for (int v = 0; v < 4; v++) { aR[mt][nt][v] = 0.f; aU[mt][nt][v] = 0.f; }
#pragma unroll
    for (int ktp = 0; ktp < 2; ktp++) {
        uint4 bRx[2], bRs[2], bUx[2], bUs[2];
#pragma unroll
        for (int nt = 0; nt < 2; nt++) {
            int nr = 2 * nq + nt, nu = nr + 8;
            bRx[nt] = *(const uint4*)&gWl[(nr * 2 + ktp) * 128 + lane * 4];
            bRs[nt] = *(const uint4*)&gWl[((16 + nr) * 2 + ktp) * 128 + lane * 4];
            bUx[nt] = *(const uint4*)&gWl[(nu * 2 + ktp) * 128 + lane * 4];
            bUs[nt] = *(const uint4*)&gWl[((16 + nu) * 2 + ktp) * 128 + lane * 4];
        }
#pragma unroll
        for (int k2 = 0; k2 < 2; k2++) {
            int kt = 2 * ktp + k2;
            uint4 as2[2];
#pragma unroll
            for (int mt = 0; mt < 2; mt++)
                as2[mt] = *(const uint4*)&Sf[((2 * mp + mt) * 4 + kt) * 128 + lane * 4];
#pragma unroll
            for (int nt = 0; nt < 2; nt++) {
                uint32 rx0 = k2 ? bRx[nt].z : bRx[nt].x, rx1 = k2 ? bRx[nt].w : bRx[nt].y;
                uint32 rs0 = k2 ? bRs[nt].z : bRs[nt].x, rs1 = k2 ? bRs[nt].w : bRs[nt].y;
                uint32 ux0 = k2 ? bUx[nt].z : bUx[nt].x, ux1 = k2 ? bUx[nt].w : bUx[nt].y;
                uint32 us0 = k2 ? bUs[nt].z : bUs[nt].x, us1 = k2 ? bUs[nt].w : bUs[nt].y;
#pragma unroll
                for (int mt = 0; mt < 2; mt++) {
                    mma_f16(aR[mt][nt], ax[mt][kt], rx0, rx1);
                    mma_f16(aR[mt][nt], as2[mt], rs0, rs1);
                    mma_f16(aU[mt][nt], ax[mt][kt], ux0, ux1);
                    mma_f16(aU[mt][nt], as2[mt], us0, us1);
                }
            }
        }
    }
}

__device__ __forceinline__ void epiA(
        const float (&aR)[2][2][4], const float (&aU)[2][2][4],
        const float (&bgr)[2][2], const float (&bgu)[2][2],
        const float (&sr)[2][2][4], float (&uv)[2][2][4],
        uint32* __restrict__ Rf, int mp, int nq, int g, int tig) {
#pragma unroll
    for (int mt = 0; mt < 2; mt++) {
        uint32 o[4];
#pragma unroll
        for (int nt = 0; nt < 2; nt++) {
            float r0 = sigm_a(aR[mt][nt][0] + bgr[nt][0]);
            float r1 = sigm_a(aR[mt][nt][1] + bgr[nt][1]);
            float r2 = sigm_a(aR[mt][nt][2] + bgr[nt][0]);
            float r3 = sigm_a(aR[mt][nt][3] + bgr[nt][1]);
            uv[mt][nt][0] = sigm_a(aU[mt][nt][0] + bgu[nt][0]);
            uv[mt][nt][1] = sigm_a(aU[mt][nt][1] + bgu[nt][1]);
            uv[mt][nt][2] = sigm_a(aU[mt][nt][2] + bgu[nt][0]);
            uv[mt][nt][3] = sigm_a(aU[mt][nt][3] + bgu[nt][1]);
            o[2 * nt + 0] = packh2(r0 * sr[mt][nt][0], r1 * sr[mt][nt][1]);
            o[2 * nt + 1] = packh2(r2 * sr[mt][nt][2], r3 * sr[mt][nt][3]);
        }
        *(uint4*)&Rf[((2 * mp + mt) * 4 + nq) * 128 + (4 * g + tig) * 4] =
            make_uint4(o[0], o[1], o[2], o[3]);
    }
}

__device__ __forceinline__ void phaseB_c(
        const uint4 (&ax)[2][4], const uint32* __restrict__ Rf,
        const uint32* __restrict__ cWl, float (&aC)[2][2][4], int lane, int mp, int nq) {
#pragma unroll
    for (int mt = 0; mt < 2; mt++)
#pragma unroll
        for (int nt = 0; nt < 2; nt++)
#pragma unroll
            for (int v = 0; v < 4; v++) aC[mt][nt][v] = 0.f;
#pragma unroll
    for (int ktp = 0; ktp < 2; ktp++) {
        uint4 bCx[2], bCs[2];
#pragma unroll
        for (int nt = 0; nt < 2; nt++) {
            int nc = 2 * nq + nt;
            bCx[nt] = *(const uint4*)&cWl[(nc * 2 + ktp) * 128 + lane * 4];
            bCs[nt] = *(const uint4*)&cWl[((8 + nc) * 2 + ktp) * 128 + lane * 4];
        }
#pragma unroll
        for (int k2 = 0; k2 < 2; k2++) {
            int kt = 2 * ktp + k2;
            uint4 ar[2];
#pragma unroll
            for (int mt = 0; mt < 2; mt++)
                ar[mt] = *(const uint4*)&Rf[((2 * mp + mt) * 4 + kt) * 128 + lane * 4];
#pragma unroll
            for (int nt = 0; nt < 2; nt++) {
                uint32 x0 = k2 ? bCx[nt].z : bCx[nt].x, x1 = k2 ? bCx[nt].w : bCx[nt].y;
                uint32 s0 = k2 ? bCs[nt].z : bCs[nt].x, s1 = k2 ? bCs[nt].w : bCs[nt].y;
#pragma unroll
                for (int mt = 0; mt < 2; mt++) {
                    mma_f16(aC[mt][nt], ax[mt][kt], x0, x1);
                    mma_f16(aC[mt][nt], ar[mt], s0, s1);
                }
            }
        }
    }
}

__device__ __forceinline__ void epiB(
        const float (&aC)[2][2][4], const float (&bcc)[2][2],
        const float (&uv)[2][2][4], float (&sr)[2][2][4],
        uint32* __restrict__ Sf, int mp, int nq, int g, int tig) {
#pragma unroll
    for (int mt = 0; mt < 2; mt++) {
        uint32 o[4];
#pragma unroll
        for (int nt = 0; nt < 2; nt++) {
            float c0 = tanh_fast(aC[mt][nt][0] + bcc[nt][0]);
            float c1 = tanh_fast(aC[mt][nt][1] + bcc[nt][1]);
            float c2 = tanh_fast(aC[mt][nt][2] + bcc[nt][0]);
            float c3 = tanh_fast(aC[mt][nt][3] + bcc[nt][1]);
            float n0 = fmaf(uv[mt][nt][0], sr[mt][nt][0] - c0, c0);
            float n1 = fmaf(uv[mt][nt][1], sr[mt][nt][1] - c1, c1);
            float n2 = fmaf(uv[mt][nt][2], sr[mt][nt][2] - c2, c2);
            float n3 = fmaf(uv[mt][nt][3], sr[mt][nt][3] - c3, c3);
            sr[mt][nt][0] = n0; sr[mt][nt][1] = n1;
            sr[mt][nt][2] = n2; sr[mt][nt][3] = n3;
            o[2 * nt + 0] = packh2(n0, n1);
            o[2 * nt + 1] = packh2(n2, n3);
        }
        *(uint4*)&Sf[((2 * mp + mt) * 4 + nq) * 128 + (4 * g + tig) * 4] =
            make_uint4(o[0], o[1], o[2], o[3]);
    }
}

// ---------------- fused 2-layer DCGRU scan + FC_out tail ----------------
__global__ __launch_bounds__(256, 1) void k_scan(
        const float* __restrict__ bg1_, const float* __restrict__ bc1_,
        const float* __restrict__ bg2_, const float* __restrict__ bc2_,
        const float* __restrict__ Wo1, const float* __restrict__ bo1,
        const float* __restrict__ Wo2, const float* __restrict__ bo2,
        float* __restrict__ out) {
    extern __shared__ uint32 smu[];
    uint32* gW0 = smu;
    uint32* gW1 = smu + 8192;
    uint32* cW0 = smu + 16384;
    uint32* cW1 = smu + 20480;
    uint32* Xf  = smu + 24576;
    uint32* S1f = smu + 28672;
    uint32* S2f = smu + 32768;
    uint32* Rf1 = smu + 34816;
    uint32* Rf2 = smu + 36864;
    float*  sb  = (float*)(smu + 38912);
    float*  oW1 = (float*)(smu + 39296);
    float*  oW2 = (float*)(smu + 43392);
    float*  ob1 = (float*)(smu + 44160);
    float*  ob2 = (float*)(smu + 44224);

    int tid = threadIdx.x;
    {
        const uint4* s0 = (const uint4*)g_gWh[0];
        const uint4* s1 = (const uint4*)g_gWh[1];
        uint4* d0 = (uint4*)gW0; uint4* d1 = (uint4*)gW1;
        for (int i = tid; i < 2048; i += 256) { d0[i] = s0[i]; d1[i] = s1[i]; }
        const uint4* c0 = (const uint4*)g_cWh[0];
        const uint4* c1 = (const uint4*)g_cWh[1];
        uint4* e0 = (uint4*)cW0; uint4* e1 = (uint4*)cW1;
        for (int i = tid; i < 1024; i += 256) { e0[i] = c0[i]; e1[i] = c1[i]; }
        for (int i = tid; i < 4096; i += 256) oW1[i] = Wo1[i];
        for (int i = tid; i < 768; i += 256) oW2[i] = Wo2[i];
        if (tid < 64) ob1[tid] = bo1[tid];
        if (tid < 12) ob2[tid] = bo2[tid];
    }
    if (tid < 128) { sb[tid] = bg1_[tid]; sb[128 + tid] = bg2_[tid]; }
    if (tid < 64)  { sb[256 + tid] = bc1_[tid]; sb[320 + tid] = bc2_[tid]; }
    {
        uint4 z = make_uint4(0, 0, 0, 0);
        uint4* z1 = (uint4*)S1f; uint4* z2 = (uint4*)S2f;
        for (int i = tid; i < 1024; i += 256) z1[i] = z;
        for (int i = tid; i < 512; i += 256) z2[i] = z;
    }
    int row0 = blockIdx.x * 64;
    int b = row0 >> 10, ntb = (row0 >> 6) & 15;
    {
        const uint4* s0 = (const uint4*)&g_XeH[(size_t)(b * Pk * 16 + ntb) * 2048];
        const uint4* s1 = (const uint4*)&g_XeH[(size_t)((b * Pk + 1) * 16 + ntb) * 2048];
        uint4* d0 = (uint4*)Xf;
        uint4* d1 = (uint4*)(Xf + 2048);
        d0[tid] = s0[tid]; d0[tid + 256] = s0[tid + 256];
        d1[tid] = s1[tid]; d1[tid + 256] = s1[tid + 256];
    }
    __syncthreads();

    int lane = tid & 31, w = tid >> 5;
    int mp = w & 1, nq = w >> 1, g = lane >> 2, tig = lane & 3;

    float bgr1[2][2], bgu1[2][2], bcc1[2][2];
    float bgr2[2][2], bgu2[2][2], bcc2[2][2];
#pragma unroll
    for (int nt = 0; nt < 2; nt++) {
        int j = 16 * nq + 8 * nt + 2 * tig;
        bgr1[nt][0] = sb[j];           bgr1[nt][1] = sb[j + 1];
        bgu1[nt][0] = sb[64 + j];      bgu1[nt][1] = sb[64 + j + 1];
        bgr2[nt][0] = sb[128 + j];     bgr2[nt][1] = sb[128 + j + 1];
        bgu2[nt][0] = sb[192 + j];     bgu2[nt][1] = sb[192 + j + 1];
        bcc1[nt][0] = sb[256 + j];     bcc1[nt][1] = sb[256 + j + 1];
        bcc2[nt][0] = sb[320 + j];     bcc2[nt][1] = sb[320 + j + 1];
    }
    float s1r[2][2][4], s2r[2][2][4];
#pragma unroll
    for (int mt = 0; mt < 2; mt++)
#pragma unroll
        for (int nt = 0; nt < 2; nt++)
#pragma unroll
            for (int v = 0; v < 4; v++) { s1r[mt][nt][v] = 0.f; s2r[mt][nt][v] = 0.f; }

    float uv1[2][2][4], uv2[2][2][4];
    uint4 xf1[2][4], xf2[2][4];

    // ---- standalone L1 at t=0 ----
    loadA2(Xf, xf1, lane, mp);
    {
        float aR[2][2][4], aU[2][2][4];
        phaseA_c(xf1, S1f + 2048, gW0, aR, aU, lane, mp, nq);
        epiA(aR, aU, bgr1, bgu1, s1r, uv1, Rf1, mp, nq, g, tig);
    }
    __syncthreads();
    {
        float aC[2][2][4];
        phaseB_c(xf1, Rf1, cW0, aC, lane, mp, nq);
        epiB(aC, bcc1, uv1, s1r, S1f, mp, nq, g, tig);
    }
    __syncthreads();

    // ---- fused supersteps: L1 at t=k+1 with L2 at t=k ----
    for (int k = 0; k <= 10; k++) {
        int p = k & 1;
        uint32* Xc  = Xf + ((k + 1) & 1) * 2048;
        uint32* S1c = S1f + p * 2048;
        uint32* S1n = S1f + (p ^ 1) * 2048;
        loadA2(Xc, xf1, lane, mp);
        loadA2(S1c, xf2, lane, mp);
        if (k + 2 < Pk) {
            const uint4* s = (const uint4*)&g_XeH[(size_t)((b * Pk + k + 2) * 16 + ntb) * 2048];
            uint4* dst = (uint4*)(Xf + (k & 1) * 2048);
            uint32 sa = (uint32)__cvta_generic_to_shared(&dst[tid]);
            asm volatile("cp.async.cg.shared.global [%0], [%1], 16;"
                         :: "r"(sa), "l"(s + tid) : "memory");
            asm volatile("cp.async.cg.shared.global [%0], [%1], 16;"
                         :: "r"(sa + 4096), "l"(s + tid + 256) : "memory");
            asm volatile("cp.async.commit_group;" ::: "memory");
        }
        {
            float aR[2][2][4], aU[2][2][4];
            phaseA_c(xf1, S1c, gW0, aR, aU, lane, mp, nq);
            epiA(aR, aU, bgr1, bgu1, s1r, uv1, Rf1, mp, nq, g, tig);
        }
        {
            float aR[2][2][4], aU[2][2][4];
            phaseA_c(xf2, S2f, gW1, aR, aU, lane, mp, nq);
            epiA(aR, aU, bgr2, bgu2, s2r, uv2, Rf2, mp, nq, g, tig);
        }
        __syncthreads();
        {
            float aC[2][2][4];
            phaseB_c(xf1, Rf1, cW0, aC, lane, mp, nq);
            epiB(aC, bcc1, uv1, s1r, S1n, mp, nq, g, tig);
        }
        {
            float aC[2][2][4];
            phaseB_c(xf2, Rf2, cW1, aC, lane, mp, nq);
            epiB(aC, bcc2, uv2, s2r, S2f, mp, nq, g, tig);
        }
        asm volatile("cp.async.wait_group 0;" ::: "memory");
        __syncthreads();
    }

    // ---- standalone L2 at t=11 ----
    loadA2(S1f + 2048, xf2, lane, mp);
    {
        float aR[2][2][4], aU[2][2][4];
        phaseA_c(xf2, S2f, gW1, aR, aU, lane, mp, nq);
        epiA(aR, aU, bgr2, bgu2, s2r, uv2, Rf2, mp, nq, g, tig);
    }
    __syncthreads();
    {
        float aC[2][2][4];
        phaseB_c(xf2, Rf2, cW1, aC, lane, mp, nq);
        epiB(aC, bcc2, uv2, s2r, S2f, mp, nq, g, tig);
    }

    // ---- FC_out tail ----
    __syncthreads();
    float* hS = (float*)gW0;   // 64 x 68
    float* sH = (float*)gW1;   // 64 x 65
#pragma unroll
    for (int mt = 0; mt < 2; mt++) {
#pragma unroll
        for (int nt = 0; nt < 2; nt++) {
            int j = 16 * nq + 8 * nt + 2 * tig;
            int rl = (2 * mp + mt) * 16 + g;
            *(float2*)&hS[rl * 68 + j]       = make_float2(s2r[mt][nt][0], s2r[mt][nt][1]);
            *(float2*)&hS[(rl + 8) * 68 + j] = make_float2(s2r[mt][nt][2], s2r[mt][nt][3]);
        }
    }
    __syncthreads();
    {
        int c0 = lane * 2;
        float acc[8][2];
#pragma unroll
        for (int ri = 0; ri < 8; ri++) { acc[ri][0] = 0.f; acc[ri][1] = 0.f; }
#pragma unroll 8
        for (int k = 0; k < 64; k++) {
            float2 wv = *(const float2*)&oW1[k * 64 + c0];
#pragma unroll
            for (int ri = 0; ri < 8; ri++) {
                float h = hS[(w + ri * 8) * 68 + k];
                acc[ri][0] = fmaf(h, wv.x, acc[ri][0]);
                acc[ri][1] = fmaf(h, wv.y, acc[ri][1]);
            }
        }
#pragma unroll
        for (int ri = 0; ri < 8; ri++) {
            int i = w + ri * 8;
            sH[i * 65 + c0]     = fmaxf(acc[ri][0] + ob1[c0], 0.f);
            sH[i * 65 + c0 + 1] = fmaxf(acc[ri][1] + ob1[c0 + 1], 0.f);
        }
    }
    __syncthreads();
    {
        int i = tid >> 2;
        int q0 = (tid & 3) * 3;
        float a0 = ob2[q0], a1 = ob2[q0 + 1], a2 = ob2[q0 + 2];
#pragma unroll 8
        for (int k = 0; k < 64; k++) {
            float h = sH[i * 65 + k];
            a0 = fmaf(h, oW2[k * 12 + q0],     a0);
            a1 = fmaf(h, oW2[k * 12 + q0 + 1], a1);
            a2 = fmaf(h, oW2[k * 12 + q0 + 2], a2);
        }
        int r = row0 + i, bb = r >> 10, n = r & 1023;
        out[(((size_t)bb * Qk + q0)     << 10) + n] = a0;
        out[(((size_t)bb * Qk + q0 + 1) << 10) + n] = a1;
        out[(((size_t)bb * Qk + q0 + 2) << 10) + n] = a2;
    }
}

// ---------------- launch ----------------
extern "C" void kernel_launch(void* const* d_in, const int* in_sizes, int n_in,
                              void* d_out, int out_size) {
    const float* X     = (const float*)d_in[0];
    const float* SE    = (const float*)d_in[3];
    const float* W_se1 = (const float*)d_in[4];  const float* b_se1 = (const float*)d_in[5];
    const float* W_se2 = (const float*)d_in[6];  const float* b_se2 = (const float*)d_in[7];
    const float* W_te1 = (const float*)d_in[8];  const float* b_te1 = (const float*)d_in[9];
    const float* W_te2 = (const float*)d_in[10]; const float* b_te2 = (const float*)d_in[11];
    const float* W_in1 = (const float*)d_in[12]; const float* b_in1 = (const float*)d_in[13];
    const float* W_in2 = (const float*)d_in[14]; const float* b_in2 = (const float*)d_in[15];
    const float* Wg1   = (const float*)d_in[16]; const float* bg1   = (const float*)d_in[17];
    const float* Wc1   = (const float*)d_in[18]; const float* bc1   = (const float*)d_in[19];
    const float* Wg2   = (const float*)d_in[20]; const float* bg2   = (const float*)d_in[21];
    const float* Wc2   = (const float*)d_in[22]; const float* bc2   = (const float*)d_in[23];
    const float* W_o1  = (const float*)d_in[24]; const float* b_o1  = (const float*)d_in[25];
    const float* W_o2  = (const float*)d_in[26]; const float* b_o2  = (const float*)d_in[27];
    const int*   TE    = (const int*)d_in[28];
    float* out = (float*)d_out;

    const size_t scan_smem = (size_t)44240 * 4;   // 176,960 B
    cudaFuncSetAttribute(k_scan, cudaFuncAttributeMaxDynamicSharedMemorySize,
                         (int)scan_smem);

    k_setup<<<561, 256>>>(Wg1, Wc1, Wg2, Wc2,
                          W_in1, b_in1, W_in2, b_in2,
                          SE, W_se1, b_se1, W_se2, b_se2,
                          TE, W_te1, b_te1, W_te2, b_te2);
    k_fc_in_h<<<Bk * Pk, 256>>>(X);
    k_scan<<<Bk * Nk / 64, 256, scan_smem>>>(bg1, bc1, bg2, bc2,
                                             W_o1, b_o1, W_o2, b_o2, out);
}

// round 16
// speedup vs baseline: 1.3423x; 1.0277x over previous
#include <cuda_runtime.h>
#include <cuda_fp16.h>

#define Bk 64
#define Pk 12
#define Qk 12
#define Nk 1024
#define Dk 64

typedef unsigned int uint32;

__device__ __forceinline__ uint32 packh2(float a, float b) {
    __half2 h = __floats2half2_rn(a, b);
    return *(uint32*)&h;
}
__device__ __forceinline__ void mma_f16(float* d, uint4 a, uint32 b0, uint32 b1) {
    asm("mma.sync.aligned.m16n8k16.row.col.f32.f16.f16.f32 "
        "{%0,%1,%2,%3},{%4,%5,%6,%7},{%8,%9},{%0,%1,%2,%3};"
        : "+f"(d[0]), "+f"(d[1]), "+f"(d[2]), "+f"(d[3])
        : "r"(a.x), "r"(a.y), "r"(a.z), "r"(a.w), "r"(b0), "r"(b1));
}
__device__ __forceinline__ float tanh_a(float z) {
    float y;
    asm("tanh.approx.f32 %0, %1;" : "=f"(y) : "f"(z));
    return y;
}
__device__ __forceinline__ float sigm_a(float z) {
    return fmaf(0.5f, tanh_a(0.5f * z), 0.5f);
}
__device__ __forceinline__ float tanh_fast(float z) {
    z = fminf(fmaxf(z, -15.f), 15.f);
    float e = __expf(-2.f * z);
    return __fdividef(1.f - e, 1.f + e);
}

// ---------------- scratch ----------------
__device__ float g_se[Nk * Dk];
__device__ float g_te[Bk * Pk * Dk];
__device__ uint32 g_gWh[2][8192];
__device__ uint32 g_cWh[2][4096];
__device__ float g_alpha[65 * 64];
__device__ float g_beta[65 * 64];
__device__ float g_ts[64];

// ---------------- fused setup ----------------
// bid 0..47   : weight folding + fp16 frag packing
// bid 48..112 : fc_in piecewise-linear table, one segment per block
// bid 113..368: spatial embedding (4 rows/block)
// bid 369..560: temporal embedding (4 rows/block)
__global__ __launch_bounds__(256) void k_setup(
        const float* __restrict__ Wg1, const float* __restrict__ Wc1,
        const float* __restrict__ Wg2, const float* __restrict__ Wc2,
        const float* __restrict__ Wi1, const float* __restrict__ bi1,
        const float* __restrict__ Wi2, const float* __restrict__ bi2,
        const float* __restrict__ SE,
        const float* __restrict__ Wse1, const float* __restrict__ bse1,
        const float* __restrict__ Wse2, const float* __restrict__ bse2,
        const int* __restrict__ TE,
        const float* __restrict__ Wte1, const float* __restrict__ bte1,
        const float* __restrict__ Wte2, const float* __restrict__ bte2) {
    __shared__ float sh[512];
    __shared__ int shi[64];
    int bid = blockIdx.x;
    int t = threadIdx.x;
    if (bid < 48) {
        int tid = bid * 256 + t;
        int stride = 48 * 256;
        for (int i = tid; i < 16384; i += stride) {
            int v = i & 3, lane = (i >> 2) & 31, ktp = (i >> 7) & 1;
            int n8 = (i >> 8) & 15, pt = (i >> 12) & 1, l = (i >> 13) & 1;
            int kt = 2 * ktp + (v >> 1), reg = v & 1;
            int g = lane >> 2, tig = lane & 3;
            int k0 = kt * 16 + 2 * tig + 8 * reg;
            int n = n8 * 8 + g;
            const float* W = l ? Wg2 : Wg1;
            int r0 = pt * 64;
            float f0 = W[(r0 + k0) * 128 + n] + W[(r0 + 128 + k0) * 128 + n];
            float f1 = W[(r0 + k0 + 1) * 128 + n] + W[(r0 + 129 + k0) * 128 + n];
            g_gWh[l][((pt * 16 + n8) * 2 + ktp) * 128 + lane * 4 + v] = packh2(f0, f1);
        }
        for (int i = tid; i < 8192; i += stride) {
            int v = i & 3, lane = (i >> 2) & 31, ktp = (i >> 7) & 1;
            int n8 = (i >> 8) & 7, pt = (i >> 11) & 1, l = (i >> 12) & 1;
            int kt = 2 * ktp + (v >> 1), reg = v & 1;
            int g = lane >> 2, tig = lane & 3;
            int k0 = kt * 16 + 2 * tig + 8 * reg;
            int n = n8 * 8 + g;
            const float* W = l ? Wc2 : Wc1;
            int r0 = pt * 64;
            float f0 = W[(r0 + k0) * 64 + n] + W[(r0 + 128 + k0) * 64 + n];
            float f1 = W[(r0 + k0 + 1) * 64 + n] + W[(r0 + 129 + k0) * 64 + n];
            g_cWh[l][((pt * 8 + n8) * 2 + ktp) * 128 + lane * 4 + v] = packh2(f0, f1);
        }
    } else if (bid < 113) {
        int s = bid - 48;
        float* w1s = sh;
        float* b1s = sh + 64;
        float* tsr = sh + 128;
        if (t < 64) { w1s[t] = Wi1[t]; b1s[t] = bi1[t]; }
        __syncthreads();
        if (t < 64) {
            float w = w1s[t];
            tsr[t] = (w != 0.f) ? (-b1s[t] / w) : __int_as_float(0x7f800000);
        }
        __syncthreads();
        if (t < 64) {
            float tv = tsr[t];
            int r = 0;
            for (int d = 0; d < 64; d++) {
                float td = tsr[d];
                r += (td < tv) || (td == tv && d < t);
            }
            shi[t] = r;
            if (s == 0) g_ts[r] = tv;
        }
        __syncthreads();
        if (t < 64) {
            int c = t;
            float a = 0.f, bt = 0.f;
            for (int d = 0; d < 64; d++) {
                float w = w1s[d];
                bool act = (w > 0.f) ? (shi[d] < s)
                         : ((w < 0.f) ? (shi[d] >= s) : (b1s[d] > 0.f));
                if (act) {
                    float w2 = Wi2[d * 64 + c];
                    a = fmaf(w, w2, a);
                    bt = fmaf(b1s[d], w2, bt);
                }
            }
            g_alpha[s * 64 + c] = a;
            g_beta[s * 64 + c] = bt + bi2[c];
        }
    } else if (bid < 369) {
        float* xs = sh;
        float* hs = sh + 256;
        int nl = t >> 6, d = t & 63;
        int n = (bid - 113) * 4 + nl;
        xs[nl * 64 + d] = SE[n * 64 + d];
        __syncthreads();
        float a = bse1[d];
#pragma unroll 8
        for (int k = 0; k < 64; k++) a = fmaf(xs[nl * 64 + k], Wse1[k * 64 + d], a);
        hs[nl * 64 + d] = fmaxf(a, 0.f);
        __syncthreads();
        float o = bse2[d];
#pragma unroll 8
        for (int k = 0; k < 64; k++) o = fmaf(hs[nl * 64 + k], Wse2[k * 64 + d], o);
        g_se[n * 64 + d] = o;
    } else {
        float* hs = sh;
        int rl = t >> 6, d = t & 63;
        int row = (bid - 369) * 4 + rl;
        int b = row / Pk, p = row - b * Pk;
        int base = (b * (Pk + Qk) + p) * 2;
        int t0 = TE[base], t1 = TE[base + 1];
        float a = Wte1[t0 * 64 + d] + Wte1[(7 + t1) * 64 + d] + bte1[d];
        hs[rl * 64 + d] = fmaxf(a, 0.f);
        __syncthreads();
        float o = bte2[d];
#pragma unroll 8
        for (int k = 0; k < 64; k++) o = fmaf(hs[rl * 64 + k], Wte2[k * 64 + d], o);
        g_te[row * 64 + d] = o;
    }
}

// ---------------- in-scan fc_in install: compute x(t) tile into frag buffer ----------------
__device__ __forceinline__ void install_x(
        uint32* __restrict__ Xdst, int t,
        const float* __restrict__ sA, const float* __restrict__ sB,
        const float* __restrict__ sSe, const float* __restrict__ sTe,
        const float* __restrict__ sXv, const int* __restrict__ sSeg,
        int tid) {
    int s = tid & 31, wu = tid >> 5;
    int g = s >> 2, tig = s & 3;
#pragma unroll
    for (int j = 0; j < 2; j++) {
        int tile = 2 * wu + j;
        int mt = tile >> 2, kt = tile & 3;
        int ra = 16 * mt + g, rb = ra + 8;
        int c0 = 16 * kt + 2 * tig, c1 = c0 + 8;
        float xa = sXv[t * 64 + ra], xb = sXv[t * 64 + rb];
        int sa_ = sSeg[t * 64 + ra] * 64, sb_ = sSeg[t * 64 + rb] * 64;
        float2 te0 = *(const float2*)&sTe[t * 64 + c0];
        float2 te1 = *(const float2*)&sTe[t * 64 + c1];
        float2 Aa0 = *(const float2*)&sA[sa_ + c0], Ba0 = *(const float2*)&sB[sa_ + c0];
        float2 Aa1 = *(const float2*)&sA[sa_ + c1], Ba1 = *(const float2*)&sB[sa_ + c1];
        float2 Ab0 = *(const float2*)&sA[sb_ + c0], Bb0 = *(const float2*)&sB[sb_ + c0];
        float2 Ab1 = *(const float2*)&sA[sb_ + c1], Bb1 = *(const float2*)&sB[sb_ + c1];
        float2 sea0 = *(const float2*)&sSe[ra * 64 + c0];
        float2 sea1 = *(const float2*)&sSe[ra * 64 + c1];
        float2 seb0 = *(const float2*)&sSe[rb * 64 + c0];
        float2 seb1 = *(const float2*)&sSe[rb * 64 + c1];
        uint32 u0 = packh2(fmaf(xa, Aa0.x, Ba0.x) + sea0.x + te0.x,
                           fmaf(xa, Aa0.y, Ba0.y) + sea0.y + te0.y);
        uint32 u1 = packh2(fmaf(xb, Ab0.x, Bb0.x) + seb0.x + te0.x,
                           fmaf(xb, Ab0.y, Bb0.y) + seb0.y + te0.y);
        uint32 u2 = packh2(fmaf(xa, Aa1.x, Ba1.x) + sea1.x + te1.x,
                           fmaf(xa, Aa1.y, Ba1.y) + sea1.y + te1.y);
        uint32 u3 = packh2(fmaf(xb, Ab1.x, Bb1.x) + seb1.x + te1.x,
                           fmaf(xb, Ab1.y, Bb1.y) + seb1.y + te1.y);
        *(uint4*)&Xdst[tile * 128 + s * 4] = make_uint4(u0, u1, u2, u3);
    }
}

// ---------------- GRU phase helpers ----------------
__device__ __forceinline__ void loadA2(const uint32* __restrict__ buf,
                                       uint4 (&f)[2][4], int lane, int mp) {
#pragma unroll
    for (int mt = 0; mt < 2; mt++)
#pragma unroll
        for (int kt = 0; kt < 4; kt++)
            f[mt][kt] = *(const uint4*)&buf[((2 * mp + mt) * 4 + kt) * 128 + lane * 4];
}

__device__ __forceinline__ void phaseA_c(
        const uint4 (&ax)[2][4], const uint32* __restrict__ Sf,
        const uint32* __restrict__ gWl,
        float (&aR)[2][2][4], float (&aU)[2][2][4], int lane, int mp, int nq) {
#pragma unroll
    for (int mt = 0; mt < 2; mt++)
#pragma unroll
        for (int nt = 0; nt < 2; nt++)
#pragma unroll
            for (int v = 0; v < 4; v++) { aR[mt][nt][v] = 0.f; aU[mt][nt][v] = 0.f; }
#pragma unroll
    for (int ktp = 0; ktp < 2; ktp++) {
        uint4 bRx[2], bRs[2], bUx[2], bUs[2];
#pragma unroll
        for (int nt = 0; nt < 2; nt++) {
            int nr = 2 * nq + nt, nu = nr + 8;
            bRx[nt] = *(const uint4*)&gWl[(nr * 2 + ktp) * 128 + lane * 4];
            bRs[nt] = *(const uint4*)&gWl[((16 + nr) * 2 + ktp) * 128 + lane * 4];
            bUx[nt] = *(const uint4*)&gWl[(nu * 2 + ktp) * 128 + lane * 4];
            bUs[nt] = *(const uint4*)&gWl[((16 + nu) * 2 + ktp) * 128 + lane * 4];
        }
#pragma unroll
        for (int k2 = 0; k2 < 2; k2++) {
            int kt = 2 * ktp + k2;
            uint4 as2[2];
#pragma unroll
            for (int mt = 0; mt < 2; mt++)
                as2[mt] = *(const uint4*)&Sf[((2 * mp + mt) * 4 + kt) * 128 + lane * 4];
#pragma unroll
            for (int nt = 0; nt < 2; nt++) {
                uint32 rx0 = k2 ? bRx[nt].z : bRx[nt].x, rx1 = k2 ? bRx[nt].w : bRx[nt].y;
                uint32 rs0 = k2 ? bRs[nt].z : bRs[nt].x, rs1 = k2 ? bRs[nt].w : bRs[nt].y;
                uint32 ux0 = k2 ? bUx[nt].z : bUx[nt].x, ux1 = k2 ? bUx[nt].w : bUx[nt].y;
                uint32 us0 = k2 ? bUs[nt].z : bUs[nt].x, us1 = k2 ? bUs[nt].w : bUs[nt].y;
#pragma unroll
                for (int mt = 0; mt < 2; mt++) {
                    mma_f16(aR[mt][nt], ax[mt][kt], rx0, rx1);
                    mma_f16(aR[mt][nt], as2[mt], rs0, rs1);
                    mma_f16(aU[mt][nt], ax[mt][kt], ux0, ux1);
                    mma_f16(aU[mt][nt], as2[mt], us0, us1);
                }
            }
        }
    }
}

__device__ __forceinline__ void epiA(
        const float (&aR)[2][2][4], const float (&aU)[2][2][4],
        const float (&bgr)[2][2], const float (&bgu)[2][2],
        const float (&sr)[2][2][4], float (&uv)[2][2][4],
        uint32* __restrict__ Rf, int mp, int nq, int g, int tig) {
#pragma unroll
    for (int mt = 0; mt < 2; mt++) {
        uint32 o[4];
#pragma unroll
        for (int nt = 0; nt < 2; nt++) {
            float r0 = sigm_a(aR[mt][nt][0] + bgr[nt][0]);
            float r1 = sigm_a(aR[mt][nt][1] + bgr[nt][1]);
            float r2 = sigm_a(aR[mt][nt][2] + bgr[nt][0]);
            float r3 = sigm_a(aR[mt][nt][3] + bgr[nt][1]);
            uv[mt][nt][0] = sigm_a(aU[mt][nt][0] + bgu[nt][0]);
            uv[mt][nt][1] = sigm_a(aU[mt][nt][1] + bgu[nt][1]);
            uv[mt][nt][2] = sigm_a(aU[mt][nt][2] + bgu[nt][0]);
            uv[mt][nt][3] = sigm_a(aU[mt][nt][3] + bgu[nt][1]);
            o[2 * nt + 0] = packh2(r0 * sr[mt][nt][0], r1 * sr[mt][nt][1]);
            o[2 * nt + 1] = packh2(r2 * sr[mt][nt][2], r3 * sr[mt][nt][3]);
        }
        *(uint4*)&Rf[((2 * mp + mt) * 4 + nq) * 128 + (4 * g + tig) * 4] =
            make_uint4(o[0], o[1], o[2], o[3]);
    }
}

__device__ __forceinline__ void phaseB_c(
        const uint4 (&ax)[2][4], const uint32* __restrict__ Rf,
        const uint32* __restrict__ cWl, float (&aC)[2][2][4], int lane, int mp, int nq) {
#pragma unroll
    for (int mt = 0; mt < 2; mt++)
#pragma unroll
        for (int nt = 0; nt < 2; nt++)
#pragma unroll
            for (int v = 0; v < 4; v++) aC[mt][nt][v] = 0.f;
#pragma unroll
    for (int ktp = 0; ktp < 2; ktp++) {
        uint4 bCx[2], bCs[2];
#pragma unroll
        for (int nt = 0; nt < 2; nt++) {
            int nc = 2 * nq + nt;
            bCx[nt] = *(const uint4*)&cWl[(nc * 2 + ktp) * 128 + lane * 4];
            bCs[nt] = *(const uint4*)&cWl[((8 + nc) * 2 + ktp) * 128 + lane * 4];
        }
#pragma unroll
        for (int k2 = 0; k2 < 2; k2++) {
            int kt = 2 * ktp + k2;
            uint4 ar[2];
#pragma unroll
            for (int mt = 0; mt < 2; mt++)
                ar[mt] = *(const uint4*)&Rf[((2 * mp + mt) * 4 + kt) * 128 + lane * 4];
#pragma unroll
            for (int nt = 0; nt < 2; nt++) {
                uint32 x0 = k2 ? bCx[nt].z : bCx[nt].x, x1 = k2 ? bCx[nt].w : bCx[nt].y;
                uint32 s0 = k2 ? bCs[nt].z : bCs[nt].x, s1 = k2 ? bCs[nt].w : bCs[nt].y;
#pragma unroll
                for (int mt = 0; mt < 2; mt++) {
                    mma_f16(aC[mt][nt], ax[mt][kt], x0, x1);
                    mma_f16(aC[mt][nt], ar[mt], s0, s1);
                }
            }
        }
    }
}

__device__ __forceinline__ void epiB(
        const float (&aC)[2][2][4], const float (&bcc)[2][2],
        const float (&uv)[2][2][4], float (&sr)[2][2][4],
        uint32* __restrict__ Sf, int mp, int nq, int g, int tig) {
#pragma unroll
    for (int mt = 0; mt < 2; mt++) {
        uint32 o[4];
#pragma unroll
        for (int nt = 0; nt < 2; nt++) {
            float c0 = tanh_fast(aC[mt][nt][0] + bcc[nt][0]);
            float c1 = tanh_fast(aC[mt][nt][1] + bcc[nt][1]);
            float c2 = tanh_fast(aC[mt][nt][2] + bcc[nt][0]);
            float c3 = tanh_fast(aC[mt][nt][3] + bcc[nt][1]);
            float n0 = fmaf(uv[mt][nt][0], sr[mt][nt][0] - c0, c0);
            float n1 = fmaf(uv[mt][nt][1], sr[mt][nt][1] - c1, c1);
            float n2 = fmaf(uv[mt][nt][2], sr[mt][nt][2] - c2, c2);
            float n3 = fmaf(uv[mt][nt][3], sr[mt][nt][3] - c3, c3);
            sr[mt][nt][0] = n0; sr[mt][nt][1] = n1;
            sr[mt][nt][2] = n2; sr[mt][nt][3] = n3;
            o[2 * nt + 0] = packh2(n0, n1);
            o[2 * nt + 1] = packh2(n2, n3);
        }
        *(uint4*)&Sf[((2 * mp + mt) * 4 + nq) * 128 + (4 * g + tig) * 4] =
            make_uint4(o[0], o[1], o[2], o[3]);
    }
}

// ---------------- fused fc_in + 2-layer DCGRU scan + FC_out ----------------
// smem (u32 words):
//  gW0 8192 | gW1 8192 | cW0 4096 | cW1 4096 | Xf 2x2048 | S1f 2x2048 | S2f 2048 |
//  Rf1 2048 | Rf2 2048 | sb 384 | sA 4160 | sB 4160 | sSe 4096 | sTe 768 |
//  sXv 768 | sSeg 768 | sTs 64   -> 54080 words = 216,320 B
__global__ __launch_bounds__(256, 1) void k_scan(
        const float* __restrict__ bg1_, const float* __restrict__ bc1_,
        const float* __restrict__ bg2_, const float* __restrict__ bc2_,
        const float* __restrict__ Wo1, const float* __restrict__ bo1,
        const float* __restrict__ Wo2, const float* __restrict__ bo2,
        const float* __restrict__ X, float* __restrict__ out) {
    extern __shared__ uint32 smu[];
    uint32* gW0 = smu;
    uint32* gW1 = smu + 8192;
    uint32* cW0 = smu + 16384;
    uint32* cW1 = smu + 20480;
    uint32* Xf  = smu + 24576;
    uint32* S1f = smu + 28672;
    uint32* S2f = smu + 32768;
    uint32* Rf1 = smu + 34816;
    uint32* Rf2 = smu + 36864;
    float*  sb  = (float*)(smu + 38912);
    float*  sA  = (float*)(smu + 39296);
    float*  sB  = (float*)(smu + 43456);
    float*  sSe = (float*)(smu + 47616);
    float*  sTe = (float*)(smu + 51712);
    float*  sXv = (float*)(smu + 52480);
    int*    sSeg = (int*)(smu + 53248);
    float*  sTs = (float*)(smu + 54016);

    int tid = threadIdx.x;
    int row0 = blockIdx.x * 64;
    int b = row0 >> 10, n0b = row0 & (Nk - 1);
    {
        const uint4* s0 = (const uint4*)g_gWh[0];
        const uint4* s1 = (const uint4*)g_gWh[1];
        uint4* d0 = (uint4*)gW0; uint4* d1 = (uint4*)gW1;
        for (int i = tid; i < 2048; i += 256) { d0[i] = s0[i]; d1[i] = s1[i]; }
        const uint4* c0 = (const uint4*)g_cWh[0];
        const uint4* c1 = (const uint4*)g_cWh[1];
        uint4* e0 = (uint4*)cW0; uint4* e1 = (uint4*)cW1;
        for (int i = tid; i < 1024; i += 256) { e0[i] = c0[i]; e1[i] = c1[i]; }
        const float4* a4 = (const float4*)g_alpha;
        const float4* b4 = (const float4*)g_beta;
        float4* dA = (float4*)sA; float4* dB = (float4*)sB;
        for (int i = tid; i < 1040; i += 256) { dA[i] = a4[i]; dB[i] = b4[i]; }
        const float4* se4 = (const float4*)&g_se[n0b * 64];
        float4* dSe = (float4*)sSe;
        for (int i = tid; i < 1024; i += 256) dSe[i] = se4[i];
        const float4* te4 = (const float4*)&g_te[b * Pk * 64];
        float4* dTe = (float4*)sTe;
        for (int i = tid; i < 192; i += 256) dTe[i] = te4[i];
        for (int i = tid; i < 768; i += 256) {
            int t = i >> 6, ii = i & 63;
            sXv[i] = X[(size_t)(b * Pk + t) * Nk + n0b + ii];
        }
        if (tid < 64) sTs[tid] = g_ts[tid];
    }
    if (tid < 128) { sb[tid] = bg1_[tid]; sb[128 + tid] = bg2_[tid]; }
    if (tid < 64)  { sb[256 + tid] = bc1_[tid]; sb[320 + tid] = bc2_[tid]; }
    {
        uint4 z = make_uint4(0, 0, 0, 0);
        uint4* z1 = (uint4*)S1f; uint4* z2 = (uint4*)S2f;
        for (int i = tid; i < 1024; i += 256) z1[i] = z;
        for (int i = tid; i < 512; i += 256) z2[i] = z;
    }
    __syncthreads();
    // segment indices for all (t, row)
    for (int i = tid; i < 768; i += 256) {
        float x = sXv[i];
        int sg = 0;
#pragma unroll 16
        for (int k = 0; k < 64; k++) sg += (sTs[k] < x);
        sSeg[i] = sg;
    }
    __syncthreads();
    // x(0) -> Xf[0], x(1) -> Xf[1]
    install_x(Xf, 0, sA, sB, sSe, sTe, sXv, sSeg, tid);
    install_x(Xf + 2048, 1, sA, sB, sSe, sTe, sXv, sSeg, tid);
    __syncthreads();

    int lane = tid & 31, w = tid >> 5;
    int mp = w & 1, nq = w >> 1, g = lane >> 2, tig = lane & 3;

    float bgr1[2][2], bgu1[2][2], bcc1[2][2];
    float bgr2[2][2], bgu2[2][2], bcc2[2][2];
#pragma unroll
    for (int nt = 0; nt < 2; nt++) {
        int j = 16 * nq + 8 * nt + 2 * tig;
        bgr1[nt][0] = sb[j];           bgr1[nt][1] = sb[j + 1];
        bgu1[nt][0] = sb[64 + j];      bgu1[nt][1] = sb[64 + j + 1];
        bgr2[nt][0] = sb[128 + j];     bgr2[nt][1] = sb[128 + j + 1];
        bgu2[nt][0] = sb[192 + j];     bgu2[nt][1] = sb[192 + j + 1];
        bcc1[nt][0] = sb[256 + j];     bcc1[nt][1] = sb[256 + j + 1];
        bcc2[nt][0] = sb[320 + j];     bcc2[nt][1] = sb[320 + j + 1];
    }
    float s1r[2][2][4], s2r[2][2][4];
#pragma unroll
    for (int mt = 0; mt < 2; mt++)
#pragma unroll
        for (int nt = 0; nt < 2; nt++)
#pragma unroll
            for (int v = 0; v < 4; v++) { s1r[mt][nt][v] = 0.f; s2r[mt][nt][v] = 0.f; }

    float uv1[2][2][4], uv2[2][2][4];
    uint4 xf1[2][4], xf2[2][4];

    // ---- standalone L1 at t=0 ----
    loadA2(Xf, xf1, lane, mp);
    {
        float aR[2][2][4], aU[2][2][4];
        phaseA_c(xf1, S1f + 2048, gW0, aR, aU, lane, mp, nq);
        epiA(aR, aU, bgr1, bgu1, s1r, uv1, Rf1, mp, nq, g, tig);
    }
    __syncthreads();
    {
        float aC[2][2][4];
        phaseB_c(xf1, Rf1, cW0, aC, lane, mp, nq);
        epiB(aC, bcc1, uv1, s1r, S1f, mp, nq, g, tig);
    }
    __syncthreads();

    // ---- fused supersteps: L1 at t=k+1 with L2 at t=k ----
    for (int k = 0; k <= 10; k++) {
        int p = k & 1;
        uint32* Xc  = Xf + ((k + 1) & 1) * 2048;
        uint32* S1c = S1f + p * 2048;
        uint32* S1n = S1f + (p ^ 1) * 2048;
        loadA2(Xc, xf1, lane, mp);
        loadA2(S1c, xf2, lane, mp);
        {
            float aR[2][2][4], aU[2][2][4];
            phaseA_c(xf1, S1c, gW0, aR, aU, lane, mp, nq);
            epiA(aR, aU, bgr1, bgu1, s1r, uv1, Rf1, mp, nq, g, tig);
        }
        {
            float aR[2][2][4], aU[2][2][4];
            phaseA_c(xf2, S2f, gW1, aR, aU, lane, mp, nq);
            epiA(aR, aU, bgr2, bgu2, s2r, uv2, Rf2, mp, nq, g, tig);
        }
        // compute x(k+2) into the buffer read next superstep
        if (k + 2 < Pk)
            install_x(Xf + (k & 1) * 2048, k + 2, sA, sB, sSe, sTe, sXv, sSeg, tid);
        __syncthreads();
        {
            float aC[2][2][4];
            phaseB_c(xf1, Rf1, cW0, aC, lane, mp, nq);
            epiB(aC, bcc1, uv1, s1r, S1n, mp, nq, g, tig);
        }
        {
            float aC[2][2][4];
            phaseB_c(xf2, Rf2, cW1, aC, lane, mp, nq);
            epiB(aC, bcc2, uv2, s2r, S2f, mp, nq, g, tig);
        }
        __syncthreads();
    }

    // ---- standalone L2 at t=11 ----
    loadA2(S1f + 2048, xf2, lane, mp);
    {
        float aR[2][2][4], aU[2][2][4];
        phaseA_c(xf2, S2f, gW1, aR, aU, lane, mp, nq);
        epiA(aR, aU, bgr2, bgu2, s2r, uv2, Rf2, mp, nq, g, tig);
    }
    __syncthreads();
    {
        float aC[2][2][4];
        phaseB_c(xf2, Rf2, cW1, aC, lane, mp, nq);
        epiB(aC, bcc2, uv2, s2r, S2f, mp, nq, g, tig);
    }

    // ---- FC_out tail (reuse weight smem; load fc_out weights now) ----
    __syncthreads();
    float* hS   = (float*)gW0;   // 64 x 68
    float* sH   = (float*)gW1;   // 64 x 65
    float* oW1f = (float*)cW0;   // 64 x 64
    float* oW2f = (float*)cW1;   // 64 x 12 + biases
    float* ob1f = oW2f + 768;
    float* ob2f = oW2f + 832;
    for (int i = tid; i < 4096; i += 256) oW1f[i] = Wo1[i];
    for (int i = tid; i < 768; i += 256) oW2f[i] = Wo2[i];
    if (tid < 64) ob1f[tid] = bo1[tid];
    if (tid < 12) ob2f[tid] = bo2[tid];
#pragma unroll
    for (int mt = 0; mt < 2; mt++) {
#pragma unroll
        for (int nt = 0; nt < 2; nt++) {
            int j = 16 * nq + 8 * nt + 2 * tig;
            int rl = (2 * mp + mt) * 16 + g;
            *(float2*)&hS[rl * 68 + j]       = make_float2(s2r[mt][nt][0], s2r[mt][nt][1]);
            *(float2*)&hS[(rl + 8) * 68 + j] = make_float2(s2r[mt][nt][2], s2r[mt][nt][3]);
        }
    }
    __syncthreads();
    {
        int c0 = lane * 2;
        float acc[8][2];
#pragma unroll
        for (int ri = 0; ri < 8; ri++) { acc[ri][0] = 0.f; acc[ri][1] = 0.f; }
#pragma unroll 8
        for (int k = 0; k < 64; k++) {
            float2 wv = *(const float2*)&oW1f[k * 64 + c0];
#pragma unroll
            for (int ri = 0; ri < 8; ri++) {
                float h = hS[(w + ri * 8) * 68 + k];
                acc[ri][0] = fmaf(h, wv.x, acc[ri][0]);
                acc[ri][1] = fmaf(h, wv.y, acc[ri][1]);
            }
        }
#pragma unroll
        for (int ri = 0; ri < 8; ri++) {
            int i = w + ri * 8;
            sH[i * 65 + c0]     = fmaxf(acc[ri][0] + ob1f[c0], 0.f);
            sH[i * 65 + c0 + 1] = fmaxf(acc[ri][1] + ob1f[c0 + 1], 0.f);
        }
    }
    __syncthreads();
    {
        int i = tid >> 2;
        int q0 = (tid & 3) * 3;
        float a0 = ob2f[q0], a1 = ob2f[q0 + 1], a2 = ob2f[q0 + 2];
#pragma unroll 8
        for (int k = 0; k < 64; k++) {
            float h = sH[i * 65 + k];
            a0 = fmaf(h, oW2f[k * 12 + q0],     a0);
            a1 = fmaf(h, oW2f[k * 12 + q0 + 1], a1);
            a2 = fmaf(h, oW2f[k * 12 + q0 + 2], a2);
        }
        int r = row0 + i, bb = r >> 10, n = r & 1023;
        out[(((size_t)bb * Qk + q0)     << 10) + n] = a0;
        out[(((size_t)bb * Qk + q0 + 1) << 10) + n] = a1;
        out[(((size_t)bb * Qk + q0 + 2) << 10) + n] = a2;
    }
}

// ---------------- launch ----------------
extern "C" void kernel_launch(void* const* d_in, const int* in_sizes, int n_in,
                              void* d_out, int out_size) {
    const float* X     = (const float*)d_in[0];
    const float* SE    = (const float*)d_in[3];
    const float* W_se1 = (const float*)d_in[4];  const float* b_se1 = (const float*)d_in[5];
    const float* W_se2 = (const float*)d_in[6];  const float* b_se2 = (const float*)d_in[7];
    const float* W_te1 = (const float*)d_in[8];  const float* b_te1 = (const float*)d_in[9];
    const float* W_te2 = (const float*)d_in[10]; const float* b_te2 = (const float*)d_in[11];
    const float* W_in1 = (const float*)d_in[12]; const float* b_in1 = (const float*)d_in[13];
    const float* W_in2 = (const float*)d_in[14]; const float* b_in2 = (const float*)d_in[15];
    const float* Wg1   = (const float*)d_in[16]; const float* bg1   = (const float*)d_in[17];
    const float* Wc1   = (const float*)d_in[18]; const float* bc1   = (const float*)d_in[19];
    const float* Wg2   = (const float*)d_in[20]; const float* bg2   = (const float*)d_in[21];
    const float* Wc2   = (const float*)d_in[22]; const float* bc2   = (const float*)d_in[23];
    const float* W_o1  = (const float*)d_in[24]; const float* b_o1  = (const float*)d_in[25];
    const float* W_o2  = (const float*)d_in[26]; const float* b_o2  = (const float*)d_in[27];
    const int*   TE    = (const int*)d_in[28];
    float* out = (float*)d_out;

    const size_t scan_smem = (size_t)54080 * 4;   // 216,320 B
    cudaFuncSetAttribute(k_scan, cudaFuncAttributeMaxDynamicSharedMemorySize,
                         (int)scan_smem);

    k_setup<<<561, 256>>>(Wg1, Wc1, Wg2, Wc2,
                          W_in1, b_in1, W_in2, b_in2,
                          SE, W_se1, b_se1, W_se2, b_se2,
                          TE, W_te1, b_te1, W_te2, b_te2);
    k_scan<<<Bk * Nk / 64, 256, scan_smem>>>(bg1, bc1, bg2, bc2,
                                             W_o1, b_o1, W_o2, b_o2, X, out);
}